// round 1
// baseline (speedup 1.0000x reference)
#include <cuda_runtime.h>
#include <cuda_bf16.h>

// Problem constants: B=4, S=2048, D=1024, H=16, HD=64
#define B_ 4
#define H_ 16
#define S_ 2048
#define D_ 1024
#define HD_ 64

// Scratch (allocation-free rule: __device__ globals). ~128MB total.
__device__ float g_q[(size_t)B_ * H_ * S_ * HD_];   // [b,h,s,hd]
__device__ float g_k[(size_t)B_ * H_ * S_ * HD_];
__device__ float g_v[(size_t)B_ * H_ * S_ * HD_];
__device__ float g_ao[(size_t)B_ * S_ * D_];        // attention output [b*s, d]

// ----------------------------------------------------------------------------
// SGEMM: C[M,N] = A[M,K] @ Bw[K,N] + bias[N]
// 128x128 tile, TK=16, 256 threads, 8x8 micro-tile split as (4+4)x(4+4).
// MODE 1: A = Ain (x), epilogue scatters into g_q/g_k/g_v ([b,h,s,hd] layout).
// MODE 0: A = g_ao, epilogue writes C (d_out).
// ----------------------------------------------------------------------------
template <int MODE>
__global__ void __launch_bounds__(256) sgemm_k(
    const float* __restrict__ Ain, const float* __restrict__ Bw,
    const float* __restrict__ bias, float* __restrict__ C,
    int M, int N, int K)
{
    __shared__ float As[16][132];   // transposed A tile, padded
    __shared__ float Bs[16][128];

    const float* A = (MODE == 0) ? g_ao : Ain;

    const int tid = threadIdx.x;
    const int tx = tid & 15;        // col group
    const int ty = tid >> 4;        // row group
    const int bm = blockIdx.y * 128;
    const int bn = blockIdx.x * 128;

    float acc[8][8];
#pragma unroll
    for (int i = 0; i < 8; i++)
#pragma unroll
        for (int j = 0; j < 8; j++) acc[i][j] = 0.0f;

    for (int k0 = 0; k0 < K; k0 += 16) {
        // Load A tile (128 rows x 16 cols), store transposed into As[k][m]
#pragma unroll
        for (int i = 0; i < 2; i++) {
            int idx = tid + i * 256;          // 0..511
            int row = idx >> 2;               // 0..127
            int c4  = (idx & 3) << 2;         // 0,4,8,12
            float4 v = *(const float4*)&A[(size_t)(bm + row) * K + k0 + c4];
            As[c4 + 0][row] = v.x;
            As[c4 + 1][row] = v.y;
            As[c4 + 2][row] = v.z;
            As[c4 + 3][row] = v.w;
        }
        // Load B tile (16 rows x 128 cols)
#pragma unroll
        for (int i = 0; i < 2; i++) {
            int idx = tid + i * 256;
            int row = idx >> 5;               // 0..15
            int c4  = (idx & 31) << 2;        // 0..124
            *(float4*)&Bs[row][c4] =
                *(const float4*)&Bw[(size_t)(k0 + row) * N + bn + c4];
        }
        __syncthreads();

#pragma unroll
        for (int k = 0; k < 16; k++) {
            float4 a0 = *(const float4*)&As[k][ty * 4];
            float4 a1 = *(const float4*)&As[k][64 + ty * 4];
            float4 b0 = *(const float4*)&Bs[k][tx * 4];
            float4 b1 = *(const float4*)&Bs[k][64 + tx * 4];
            float a[8] = {a0.x, a0.y, a0.z, a0.w, a1.x, a1.y, a1.z, a1.w};
            float b[8] = {b0.x, b0.y, b0.z, b0.w, b1.x, b1.y, b1.z, b1.w};
#pragma unroll
            for (int i = 0; i < 8; i++)
#pragma unroll
                for (int j = 0; j < 8; j++)
                    acc[i][j] += a[i] * b[j];
        }
        __syncthreads();
    }

    // Epilogue
    if (MODE == 0) {
        float4 bb0 = *(const float4*)&bias[bn + tx * 4];
        float4 bb1 = *(const float4*)&bias[bn + 64 + tx * 4];
#pragma unroll
        for (int i = 0; i < 8; i++) {
            int m = bm + ((i < 4) ? (ty * 4 + i) : (64 + ty * 4 + i - 4));
            float* crow = C + (size_t)m * N + bn;
            float4 o0, o1;
            o0.x = acc[i][0] + bb0.x; o0.y = acc[i][1] + bb0.y;
            o0.z = acc[i][2] + bb0.z; o0.w = acc[i][3] + bb0.w;
            o1.x = acc[i][4] + bb1.x; o1.y = acc[i][5] + bb1.y;
            o1.z = acc[i][6] + bb1.z; o1.w = acc[i][7] + bb1.w;
            *(float4*)&crow[tx * 4] = o0;
            *(float4*)&crow[64 + tx * 4] = o1;
        }
    } else {
#pragma unroll
        for (int i = 0; i < 8; i++) {
            int m = bm + ((i < 4) ? (ty * 4 + i) : (64 + ty * 4 + i - 4));
            int bb = m >> 11;           // / 2048
            int s  = m & 2047;
#pragma unroll
            for (int j = 0; j < 8; j++) {
                int n = bn + ((j < 4) ? (tx * 4 + j) : (64 + tx * 4 + j - 4));
                float v = acc[i][j] + bias[n];
                int which = n >> 10;    // 0=q, 1=k, 2=v
                int d  = n & 1023;
                int h  = d >> 6;
                int hd = d & 63;
                float* dst = (which == 0) ? g_q : (which == 1) ? g_k : g_v;
                dst[(((size_t)bb * H_ + h) * S_ + s) * HD_ + hd] = v;
            }
        }
    }
}

// ----------------------------------------------------------------------------
// Flash attention, fp32, BQ=BK=64, online softmax, causal mask (analytic).
// One block per (b, h, q_tile). Big q-tiles scheduled first for balance.
// ----------------------------------------------------------------------------
#define LD 68   // padded row stride (floats): keeps 16B alignment, spreads banks
#define FLASH_SMEM_FLOATS (4 * 64 * LD + 3 * 64)
#define FLASH_SMEM_BYTES  (FLASH_SMEM_FLOATS * 4)

__global__ void __launch_bounds__(256) flash_kernel()
{
    extern __shared__ float sh[];
    float* Qs   = sh;
    float* Ks   = Qs + 64 * LD;
    float* Vs   = Ks + 64 * LD;
    float* Ss   = Vs + 64 * LD;
    float* mrow = Ss + 64 * LD;
    float* lrow = mrow + 64;
    float* arow = lrow + 64;

    const int z  = blockIdx.x;
    const int bh = z >> 5;                 // b*16 + h
    const int qt = 31 - (z & 31);          // biggest tiles first
    const int b  = bh >> 4;
    const int h  = bh & 15;

    const int tid = threadIdx.x;
    const int tx  = tid & 15;
    const int ty  = tid >> 4;

    const float NEG_INF = __int_as_float(0xff800000);

    // Load Q tile (64 x 64)
    {
        const float* qb = g_q + ((size_t)bh * S_ + qt * 64) * HD_;
#pragma unroll
        for (int i = 0; i < 4; i++) {
            int idx = tid + i * 256;       // 0..1023
            int row = idx >> 4;
            int c4  = (idx & 15) << 2;
            float4 v = *(const float4*)&qb[row * 64 + c4];
            *(float4*)&Qs[row * LD + c4] = v;
        }
    }
    if (tid < 64) { mrow[tid] = NEG_INF; lrow[tid] = 0.0f; }

    float acc[4][4];
#pragma unroll
    for (int i = 0; i < 4; i++)
#pragma unroll
        for (int j = 0; j < 4; j++) acc[i][j] = 0.0f;

    const float scale = 0.125f;            // 1/sqrt(64)

    for (int kt = 0; kt <= qt; kt++) {
        __syncthreads();   // Q ready (first iter) / previous PV done reading K,V,Ss

        // Load K, V tiles (64 x 64 each)
        const float* kb = g_k + ((size_t)bh * S_ + kt * 64) * HD_;
        const float* vb = g_v + ((size_t)bh * S_ + kt * 64) * HD_;
#pragma unroll
        for (int i = 0; i < 4; i++) {
            int idx = tid + i * 256;
            int row = idx >> 4;
            int c4  = (idx & 15) << 2;
            float4 u = *(const float4*)&kb[row * 64 + c4];
            *(float4*)&Ks[row * LD + c4] = u;
            float4 w = *(const float4*)&vb[row * 64 + c4];
            *(float4*)&Vs[row * LD + c4] = w;
        }
        __syncthreads();

        // Scores: S = Q K^T * scale  (each thread: 4x4 over k=64)
        float sacc[4][4];
#pragma unroll
        for (int i = 0; i < 4; i++)
#pragma unroll
            for (int j = 0; j < 4; j++) sacc[i][j] = 0.0f;

#pragma unroll
        for (int k = 0; k < 64; k += 4) {
            float4 qa[4], kbf[4];
#pragma unroll
            for (int i = 0; i < 4; i++)
                qa[i] = *(const float4*)&Qs[(ty * 4 + i) * LD + k];
#pragma unroll
            for (int j = 0; j < 4; j++)
                kbf[j] = *(const float4*)&Ks[(tx * 4 + j) * LD + k];
#pragma unroll
            for (int i = 0; i < 4; i++)
#pragma unroll
                for (int j = 0; j < 4; j++)
                    sacc[i][j] += qa[i].x * kbf[j].x + qa[i].y * kbf[j].y +
                                  qa[i].z * kbf[j].z + qa[i].w * kbf[j].w;
        }

        const bool diag = (kt == qt);
#pragma unroll
        for (int i = 0; i < 4; i++) {
            int r = ty * 4 + i;
#pragma unroll
            for (int j = 0; j < 4; j++) {
                int c = tx * 4 + j;
                float v = sacc[i][j] * scale;
                if (diag && c > r) v = NEG_INF;
                Ss[r * LD + c] = v;
            }
        }
        __syncthreads();

        // Online softmax (one thread per row)
        if (tid < 64) {
            int r = tid;
            float mx = mrow[r];
#pragma unroll 8
            for (int c = 0; c < 64; c++) mx = fmaxf(mx, Ss[r * LD + c]);
            float al = __expf(mrow[r] - mx);   // 0 if mrow == -inf
            float sum = 0.0f;
#pragma unroll 8
            for (int c = 0; c < 64; c++) {
                float e = __expf(Ss[r * LD + c] - mx);
                Ss[r * LD + c] = e;
                sum += e;
            }
            lrow[r] = lrow[r] * al + sum;
            mrow[r] = mx;
            arow[r] = al;
        }
        __syncthreads();

        // Rescale accumulators, then O += P V
#pragma unroll
        for (int i = 0; i < 4; i++) {
            float al = arow[ty * 4 + i];
#pragma unroll
            for (int j = 0; j < 4; j++) acc[i][j] *= al;
        }
#pragma unroll
        for (int k = 0; k < 64; k += 4) {
            float4 pa[4], vv[4];
#pragma unroll
            for (int i = 0; i < 4; i++)
                pa[i] = *(const float4*)&Ss[(ty * 4 + i) * LD + k];
#pragma unroll
            for (int kk = 0; kk < 4; kk++)
                vv[kk] = *(const float4*)&Vs[(k + kk) * LD + tx * 4];
#pragma unroll
            for (int i = 0; i < 4; i++) {
                acc[i][0] += pa[i].x * vv[0].x + pa[i].y * vv[1].x +
                             pa[i].z * vv[2].x + pa[i].w * vv[3].x;
                acc[i][1] += pa[i].x * vv[0].y + pa[i].y * vv[1].y +
                             pa[i].z * vv[2].y + pa[i].w * vv[3].y;
                acc[i][2] += pa[i].x * vv[0].z + pa[i].y * vv[1].z +
                             pa[i].z * vv[2].z + pa[i].w * vv[3].z;
                acc[i][3] += pa[i].x * vv[0].w + pa[i].y * vv[1].w +
                             pa[i].z * vv[2].w + pa[i].w * vv[3].w;
            }
        }
    }

    // Write O / l  ->  g_ao[b*s, h*64 + c]
#pragma unroll
    for (int i = 0; i < 4; i++) {
        int r  = ty * 4 + i;
        int sq = qt * 64 + r;
        float inv = 1.0f / lrow[r];
        float4 o;
        o.x = acc[i][0] * inv; o.y = acc[i][1] * inv;
        o.z = acc[i][2] * inv; o.w = acc[i][3] * inv;
        *(float4*)&g_ao[((size_t)b * S_ + sq) * D_ + h * HD_ + tx * 4] = o;
    }
}

// ----------------------------------------------------------------------------
// Launch: QKV GEMM -> flash attention -> output projection
// ----------------------------------------------------------------------------
extern "C" void kernel_launch(void* const* d_in, const int* in_sizes, int n_in,
                              void* d_out, int out_size)
{
    // Robust input mapping by element counts (all distinct):
    // x:8388608, mask:4194304 (ignored), w_attn:3145728, b_attn:3072,
    // w_proj:1048576, b_proj:1024
    const float *x = nullptr, *w_attn = nullptr, *b_attn = nullptr;
    const float *w_proj = nullptr, *b_proj = nullptr;
    for (int i = 0; i < n_in; i++) {
        switch (in_sizes[i]) {
            case 8388608: x      = (const float*)d_in[i]; break;
            case 3145728: w_attn = (const float*)d_in[i]; break;
            case 3072:    b_attn = (const float*)d_in[i]; break;
            case 1048576: w_proj = (const float*)d_in[i]; break;
            case 1024:    b_proj = (const float*)d_in[i]; break;
            default: break;  // mask
        }
    }
    // Positional fallback (metadata order: x, mask, w_attn, b_attn, w_proj, b_proj)
    if (!x)      x      = (const float*)d_in[0];
    if (!w_attn) w_attn = (const float*)d_in[2];
    if (!b_attn) b_attn = (const float*)d_in[3];
    if (!w_proj) w_proj = (const float*)d_in[4];
    if (!b_proj) b_proj = (const float*)d_in[5];

    const int M = B_ * S_;  // 8192

    // 1) QKV projection with scatter to [b,h,s,hd]
    sgemm_k<1><<<dim3(3 * D_ / 128, M / 128), 256>>>(
        x, w_attn, b_attn, nullptr, M, 3 * D_, D_);

    // 2) Fused causal flash attention
    cudaFuncSetAttribute(flash_kernel,
                         cudaFuncAttributeMaxDynamicSharedMemorySize,
                         FLASH_SMEM_BYTES);
    flash_kernel<<<B_ * H_ * (S_ / 64), 256, FLASH_SMEM_BYTES>>>();

    // 3) Output projection -> d_out
    sgemm_k<0><<<dim3(D_ / 128, M / 128), 256>>>(
        nullptr, w_proj, b_proj, (float*)d_out, M, D_, D_);
}

// round 5
// speedup vs baseline: 1.0093x; 1.0093x over previous
#include <cuda_runtime.h>
#include <cuda_bf16.h>
#include <cstdint>

// Problem constants: B=4, S=2048, D=1024, H=16, HD=64
#define B_ 4
#define H_ 16
#define S_ 2048
#define D_ 1024
#define HD_ 64

// Scratch (allocation-free rule: __device__ globals).
__device__ float g_q[(size_t)B_ * H_ * S_ * HD_];   // [b,h,s,hd]
__device__ float g_k[(size_t)B_ * H_ * S_ * HD_];
__device__ float g_v[(size_t)B_ * H_ * S_ * HD_];
__device__ float g_ao[(size_t)B_ * S_ * D_];        // attention output [b*s, d]

// ============================================================================
// fp32 SGEMM (R1, known good): C[M,N] = A[M,K] @ Bw[K,N] + bias[N]
// MODE 1: A = Ain (x), epilogue scatters into g_q/g_k/g_v ([b,h,s,hd]).
// MODE 0: A = g_ao, epilogue writes C.
// ============================================================================
template <int MODE>
__global__ void __launch_bounds__(256) sgemm_k(
    const float* __restrict__ Ain, const float* __restrict__ Bw,
    const float* __restrict__ bias, float* __restrict__ C,
    int M, int N, int K)
{
    __shared__ float As[16][132];
    __shared__ float Bs[16][128];

    const float* A = (MODE == 0) ? g_ao : Ain;

    const int tid = threadIdx.x;
    const int tx = tid & 15;
    const int ty = tid >> 4;
    const int bm = blockIdx.y * 128;
    const int bn = blockIdx.x * 128;

    float acc[8][8];
#pragma unroll
    for (int i = 0; i < 8; i++)
#pragma unroll
        for (int j = 0; j < 8; j++) acc[i][j] = 0.0f;

    for (int k0 = 0; k0 < K; k0 += 16) {
#pragma unroll
        for (int i = 0; i < 2; i++) {
            int idx = tid + i * 256;
            int row = idx >> 2;
            int c4  = (idx & 3) << 2;
            float4 v = *(const float4*)&A[(size_t)(bm + row) * K + k0 + c4];
            As[c4 + 0][row] = v.x;
            As[c4 + 1][row] = v.y;
            As[c4 + 2][row] = v.z;
            As[c4 + 3][row] = v.w;
        }
#pragma unroll
        for (int i = 0; i < 2; i++) {
            int idx = tid + i * 256;
            int row = idx >> 5;
            int c4  = (idx & 31) << 2;
            *(float4*)&Bs[row][c4] =
                *(const float4*)&Bw[(size_t)(k0 + row) * N + bn + c4];
        }
        __syncthreads();

#pragma unroll
        for (int k = 0; k < 16; k++) {
            float4 a0 = *(const float4*)&As[k][ty * 4];
            float4 a1 = *(const float4*)&As[k][64 + ty * 4];
            float4 b0 = *(const float4*)&Bs[k][tx * 4];
            float4 b1 = *(const float4*)&Bs[k][64 + tx * 4];
            float a[8] = {a0.x, a0.y, a0.z, a0.w, a1.x, a1.y, a1.z, a1.w};
            float b[8] = {b0.x, b0.y, b0.z, b0.w, b1.x, b1.y, b1.z, b1.w};
#pragma unroll
            for (int i = 0; i < 8; i++)
#pragma unroll
                for (int j = 0; j < 8; j++)
                    acc[i][j] += a[i] * b[j];
        }
        __syncthreads();
    }

    if (MODE == 0) {
        float4 bb0 = *(const float4*)&bias[bn + tx * 4];
        float4 bb1 = *(const float4*)&bias[bn + 64 + tx * 4];
#pragma unroll
        for (int i = 0; i < 8; i++) {
            int m = bm + ((i < 4) ? (ty * 4 + i) : (64 + ty * 4 + i - 4));
            float* crow = C + (size_t)m * N + bn;
            float4 o0, o1;
            o0.x = acc[i][0] + bb0.x; o0.y = acc[i][1] + bb0.y;
            o0.z = acc[i][2] + bb0.z; o0.w = acc[i][3] + bb0.w;
            o1.x = acc[i][4] + bb1.x; o1.y = acc[i][5] + bb1.y;
            o1.z = acc[i][6] + bb1.z; o1.w = acc[i][7] + bb1.w;
            *(float4*)&crow[tx * 4] = o0;
            *(float4*)&crow[64 + tx * 4] = o1;
        }
    } else {
#pragma unroll
        for (int i = 0; i < 8; i++) {
            int m = bm + ((i < 4) ? (ty * 4 + i) : (64 + ty * 4 + i - 4));
            int bb = m >> 11;
            int s  = m & 2047;
#pragma unroll
            for (int j = 0; j < 8; j++) {
                int n = bn + ((j < 4) ? (tx * 4 + j) : (64 + tx * 4 + j - 4));
                float v = acc[i][j] + bias[n];
                int which = n >> 10;
                int d  = n & 1023;
                int h  = d >> 6;
                int hd = d & 63;
                float* dst = (which == 0) ? g_q : (which == 1) ? g_k : g_v;
                dst[(((size_t)bb * H_ + h) * S_ + s) * HD_ + hd] = v;
            }
        }
    }
}

// ============================================================================
// mma.sync m16n8k16 bf16 path — OUTPUT PROJECTION ONLY this round.
// Out[8192,1024] = g_ao[8192,1024] @ w_proj[1024,1024] + b_proj.
// All staging in-kernel from raw fp32 weights (no prepass, no byte_perm).
// bf16 2-split 3-product emulation: D += Ahi*Bhi + Ahi*Blo + Alo*Bhi.
// smem: u32 k-pair arrays, stride 18 u32 -> conflict-free fragment loads.
// ============================================================================
#define MMA16816(d, a, b0, b1)                                               \
    asm volatile("mma.sync.aligned.m16n8k16.row.col.f32.bf16.bf16.f32 "      \
                 "{%0,%1,%2,%3}, {%4,%5,%6,%7}, {%8,%9}, {%0,%1,%2,%3};"     \
                 : "+f"((d)[0]), "+f"((d)[1]), "+f"((d)[2]), "+f"((d)[3])    \
                 : "r"((a)[0]), "r"((a)[1]), "r"((a)[2]), "r"((a)[3]),       \
                   "r"(b0), "r"(b1))

#define KPSTR 18   // u32 stride per row (16 kpairs + 2 pad)

__device__ __forceinline__ void split2(float x0, float x1,
                                       uint32_t& hi, uint32_t& lo) {
    __nv_bfloat16 h0 = __float2bfloat16_rn(x0);
    __nv_bfloat16 h1 = __float2bfloat16_rn(x1);
    float r0 = x0 - __bfloat162float(h0);
    float r1 = x1 - __bfloat162float(h1);
    __nv_bfloat16 l0 = __float2bfloat16_rn(r0);
    __nv_bfloat16 l1 = __float2bfloat16_rn(r1);
    hi = (uint32_t)__bfloat16_as_ushort(h0) |
         ((uint32_t)__bfloat16_as_ushort(h1) << 16);
    lo = (uint32_t)__bfloat16_as_ushort(l0) |
         ((uint32_t)__bfloat16_as_ushort(l1) << 16);
}

__global__ void __launch_bounds__(256) proj_mma(
    const float* __restrict__ W,      // w_proj [K=1024][N=1024] row-major
    const float* __restrict__ bias,   // b_proj [1024]
    float* __restrict__ Out)          // [8192][1024]
{
    __shared__ uint32_t sAhi[128][KPSTR];
    __shared__ uint32_t sAlo[128][KPSTR];
    __shared__ uint32_t sBhi[128][KPSTR];   // rows = n-local
    __shared__ uint32_t sBlo[128][KPSTR];

    const int tid = threadIdx.x;
    const int wid = tid >> 5;
    const int lane = tid & 31;
    const int g = lane >> 2;          // groupID 0..7
    const int t = lane & 3;           // thread-in-group 0..3
    const int wm = wid & 3;           // 32-row slab
    const int wn = wid >> 2;          // 64-col slab
    const int bm = blockIdx.y * 128;
    const int bn = blockIdx.x * 128;

    float acc[2][8][4];
#pragma unroll
    for (int i = 0; i < 2; i++)
#pragma unroll
        for (int j = 0; j < 8; j++)
#pragma unroll
            for (int c = 0; c < 4; c++) acc[i][j][c] = 0.0f;

    for (int kc = 0; kc < 32; kc++) {
        const int k0 = kc * 32;
        // ---- stage A: g_ao rows (k contiguous), 128 rows x 16 kpairs ----
#pragma unroll
        for (int i = 0; i < 8; i++) {
            int idx = tid + i * 256;        // 0..2047
            int row = idx >> 4;             // 0..127
            int kp  = idx & 15;             // 0..15
            float2 v = *(const float2*)&g_ao[(size_t)(bm + row) * 1024 + k0 + kp * 2];
            split2(v.x, v.y, sAhi[row][kp], sAlo[row][kp]);
        }
        // ---- stage B: transpose w[k][n] -> smem[n][kpair] ----
#pragma unroll
        for (int i = 0; i < 8; i++) {
            int idx = tid + i * 256;
            int n   = idx & 127;            // 0..127 (coalesced in n)
            int kp  = idx >> 7;             // 0..15
            float w0 = W[(size_t)(k0 + kp * 2) * 1024 + bn + n];
            float w1 = W[(size_t)(k0 + kp * 2 + 1) * 1024 + bn + n];
            split2(w0, w1, sBhi[n][kp], sBlo[n][kp]);
        }
        __syncthreads();

#pragma unroll
        for (int ks = 0; ks < 2; ks++) {
            const int kp0 = ks * 8;
            uint32_t ah[2][4], al[2][4];
#pragma unroll
            for (int mt = 0; mt < 2; mt++) {
                int r0 = wm * 32 + mt * 16 + g;
                ah[mt][0] = sAhi[r0][kp0 + t];
                ah[mt][1] = sAhi[r0 + 8][kp0 + t];
                ah[mt][2] = sAhi[r0][kp0 + t + 4];
                ah[mt][3] = sAhi[r0 + 8][kp0 + t + 4];
                al[mt][0] = sAlo[r0][kp0 + t];
                al[mt][1] = sAlo[r0 + 8][kp0 + t];
                al[mt][2] = sAlo[r0][kp0 + t + 4];
                al[mt][3] = sAlo[r0 + 8][kp0 + t + 4];
            }
#pragma unroll
            for (int nt = 0; nt < 8; nt++) {
                int nr = wn * 64 + nt * 8 + g;
                uint32_t bh0 = sBhi[nr][kp0 + t];
                uint32_t bh1 = sBhi[nr][kp0 + t + 4];
                uint32_t bl0 = sBlo[nr][kp0 + t];
                uint32_t bl1 = sBlo[nr][kp0 + t + 4];
#pragma unroll
                for (int mt = 0; mt < 2; mt++) {
                    MMA16816(acc[mt][nt], ah[mt], bh0, bh1);
                    MMA16816(acc[mt][nt], ah[mt], bl0, bl1);
                    MMA16816(acc[mt][nt], al[mt], bh0, bh1);
                }
            }
        }
        __syncthreads();
    }

    // ---- epilogue: d0/d1 -> row g, cols t*2,t*2+1; d2/d3 -> row g+8 ----
#pragma unroll
    for (int mt = 0; mt < 2; mt++) {
        int row0 = bm + wm * 32 + mt * 16 + g;
#pragma unroll
        for (int nt = 0; nt < 8; nt++) {
            int col = bn + wn * 64 + nt * 8 + t * 2;
            float b0 = bias[col], b1 = bias[col + 1];
            float2 v0 = make_float2(acc[mt][nt][0] + b0, acc[mt][nt][1] + b1);
            float2 v1 = make_float2(acc[mt][nt][2] + b0, acc[mt][nt][3] + b1);
            *(float2*)&Out[(size_t)row0 * 1024 + col] = v0;
            *(float2*)&Out[(size_t)(row0 + 8) * 1024 + col] = v1;
        }
    }
}

// ============================================================================
// Flash attention, fp32, BQ=BK=64, online softmax, causal (R1 verbatim).
// ============================================================================
#define LD 68
#define FLASH_SMEM_FLOATS (4 * 64 * LD + 3 * 64)
#define FLASH_SMEM_BYTES  (FLASH_SMEM_FLOATS * 4)

__global__ void __launch_bounds__(256) flash_kernel()
{
    extern __shared__ float sh[];
    float* Qs   = sh;
    float* Ks   = Qs + 64 * LD;
    float* Vs   = Ks + 64 * LD;
    float* Ss   = Vs + 64 * LD;
    float* mrow = Ss + 64 * LD;
    float* lrow = mrow + 64;
    float* arow = lrow + 64;

    const int z  = blockIdx.x;
    const int bh = z >> 5;
    const int qt = 31 - (z & 31);
    const int b  = bh >> 4;
    const int h  = bh & 15;

    const int tid = threadIdx.x;
    const int tx  = tid & 15;
    const int ty  = tid >> 4;

    const float NEG_INF = __int_as_float(0xff800000);

    {
        const float* qb = g_q + ((size_t)bh * S_ + qt * 64) * HD_;
#pragma unroll
        for (int i = 0; i < 4; i++) {
            int idx = tid + i * 256;
            int row = idx >> 4;
            int c4  = (idx & 15) << 2;
            *(float4*)&Qs[row * LD + c4] = *(const float4*)&qb[row * 64 + c4];
        }
    }
    if (tid < 64) { mrow[tid] = NEG_INF; lrow[tid] = 0.0f; }

    float acc[4][4];
#pragma unroll
    for (int i = 0; i < 4; i++)
#pragma unroll
        for (int j = 0; j < 4; j++) acc[i][j] = 0.0f;

    const float scale = 0.125f;

    for (int kt = 0; kt <= qt; kt++) {
        __syncthreads();
        const float* kb = g_k + ((size_t)bh * S_ + kt * 64) * HD_;
        const float* vb = g_v + ((size_t)bh * S_ + kt * 64) * HD_;
#pragma unroll
        for (int i = 0; i < 4; i++) {
            int idx = tid + i * 256;
            int row = idx >> 4;
            int c4  = (idx & 15) << 2;
            *(float4*)&Ks[row * LD + c4] = *(const float4*)&kb[row * 64 + c4];
            *(float4*)&Vs[row * LD + c4] = *(const float4*)&vb[row * 64 + c4];
        }
        __syncthreads();

        float sacc[4][4];
#pragma unroll
        for (int i = 0; i < 4; i++)
#pragma unroll
            for (int j = 0; j < 4; j++) sacc[i][j] = 0.0f;

#pragma unroll
        for (int k = 0; k < 64; k += 4) {
            float4 qa[4], kbf[4];
#pragma unroll
            for (int i = 0; i < 4; i++) qa[i] = *(const float4*)&Qs[(ty * 4 + i) * LD + k];
#pragma unroll
            for (int j = 0; j < 4; j++) kbf[j] = *(const float4*)&Ks[(tx * 4 + j) * LD + k];
#pragma unroll
            for (int i = 0; i < 4; i++)
#pragma unroll
                for (int j = 0; j < 4; j++)
                    sacc[i][j] += qa[i].x * kbf[j].x + qa[i].y * kbf[j].y +
                                  qa[i].z * kbf[j].z + qa[i].w * kbf[j].w;
        }

        const bool diag = (kt == qt);
#pragma unroll
        for (int i = 0; i < 4; i++) {
            int r = ty * 4 + i;
#pragma unroll
            for (int j = 0; j < 4; j++) {
                int c = tx * 4 + j;
                float v = sacc[i][j] * scale;
                if (diag && c > r) v = NEG_INF;
                Ss[r * LD + c] = v;
            }
        }
        __syncthreads();

        if (tid < 64) {
            int r = tid;
            float mx = mrow[r];
#pragma unroll 8
            for (int c = 0; c < 64; c++) mx = fmaxf(mx, Ss[r * LD + c]);
            float al = __expf(mrow[r] - mx);
            float sum = 0.0f;
#pragma unroll 8
            for (int c = 0; c < 64; c++) {
                float e = __expf(Ss[r * LD + c] - mx);
                Ss[r * LD + c] = e;
                sum += e;
            }
            lrow[r] = lrow[r] * al + sum;
            mrow[r] = mx;
            arow[r] = al;
        }
        __syncthreads();

#pragma unroll
        for (int i = 0; i < 4; i++) {
            float al = arow[ty * 4 + i];
#pragma unroll
            for (int j = 0; j < 4; j++) acc[i][j] *= al;
        }
#pragma unroll
        for (int k = 0; k < 64; k += 4) {
            float4 pa[4], vv[4];
#pragma unroll
            for (int i = 0; i < 4; i++) pa[i] = *(const float4*)&Ss[(ty * 4 + i) * LD + k];
#pragma unroll
            for (int kk = 0; kk < 4; kk++) vv[kk] = *(const float4*)&Vs[(k + kk) * LD + tx * 4];
#pragma unroll
            for (int i = 0; i < 4; i++) {
                acc[i][0] += pa[i].x * vv[0].x + pa[i].y * vv[1].x +
                             pa[i].z * vv[2].x + pa[i].w * vv[3].x;
                acc[i][1] += pa[i].x * vv[0].y + pa[i].y * vv[1].y +
                             pa[i].z * vv[2].y + pa[i].w * vv[3].y;
                acc[i][2] += pa[i].x * vv[0].z + pa[i].y * vv[1].z +
                             pa[i].z * vv[2].z + pa[i].w * vv[3].z;
                acc[i][3] += pa[i].x * vv[0].w + pa[i].y * vv[1].w +
                             pa[i].z * vv[2].w + pa[i].w * vv[3].w;
            }
        }
    }

#pragma unroll
    for (int i = 0; i < 4; i++) {
        int r  = ty * 4 + i;
        int sq = qt * 64 + r;
        float inv = 1.0f / lrow[r];
        float4 o;
        o.x = acc[i][0] * inv; o.y = acc[i][1] * inv;
        o.z = acc[i][2] * inv; o.w = acc[i][3] * inv;
        *(float4*)&g_ao[((size_t)b * S_ + sq) * D_ + h * HD_ + tx * 4] = o;
    }
}

// ============================================================================
// Launch: QKV (fp32 sgemm, known good) -> flash (fp32, known good)
//         -> output projection (NEW: bf16-emulated mma) 
// ============================================================================
extern "C" void kernel_launch(void* const* d_in, const int* in_sizes, int n_in,
                              void* d_out, int out_size)
{
    const float *x = nullptr, *w_attn = nullptr, *b_attn = nullptr;
    const float *w_proj = nullptr, *b_proj = nullptr;
    for (int i = 0; i < n_in; i++) {
        switch (in_sizes[i]) {
            case 8388608: x      = (const float*)d_in[i]; break;
            case 3145728: w_attn = (const float*)d_in[i]; break;
            case 3072:    b_attn = (const float*)d_in[i]; break;
            case 1048576: w_proj = (const float*)d_in[i]; break;
            case 1024:    b_proj = (const float*)d_in[i]; break;
            default: break;  // mask (ignored; causal handled analytically)
        }
    }
    if (!x)      x      = (const float*)d_in[0];
    if (!w_attn) w_attn = (const float*)d_in[2];
    if (!b_attn) b_attn = (const float*)d_in[3];
    if (!w_proj) w_proj = (const float*)d_in[4];
    if (!b_proj) b_proj = (const float*)d_in[5];

    const int M = B_ * S_;  // 8192

    cudaFuncSetAttribute(flash_kernel, cudaFuncAttributeMaxDynamicSharedMemorySize,
                         FLASH_SMEM_BYTES);

    // 1) QKV projection (fp32 SGEMM, known good) with scatter to [b,h,s,hd]
    sgemm_k<1><<<dim3(3 * D_ / 128, M / 128), 256>>>(
        x, w_attn, b_attn, nullptr, M, 3 * D_, D_);

    // 2) Fused causal flash attention (fp32, known good)
    flash_kernel<<<B_ * H_ * (S_ / 64), 256, FLASH_SMEM_BYTES>>>();

    // 3) Output projection — bf16 2-split mma (validation target this round)
    proj_mma<<<dim3(D_ / 128, M / 128), 256>>>(w_proj, b_proj, (float*)d_out);
}

// round 6
// speedup vs baseline: 1.2096x; 1.1984x over previous
#include <cuda_runtime.h>
#include <cuda_bf16.h>
#include <cstdint>

// Problem constants: B=4, S=2048, D=1024, H=16, HD=64
#define B_ 4
#define H_ 16
#define S_ 2048
#define D_ 1024
#define HD_ 64

// Scratch (allocation-free rule: __device__ globals).
__device__ float g_q[(size_t)B_ * H_ * S_ * HD_];   // [b,h,s,hd]
__device__ float g_k[(size_t)B_ * H_ * S_ * HD_];
__device__ float g_v[(size_t)B_ * H_ * S_ * HD_];
__device__ float g_ao[(size_t)B_ * S_ * D_];        // attention output [b*s, d]

// ============================================================================
// mma.sync m16n8k16 bf16 (baseline PTX; compiles for plain sm_103)
// bf16 2-split 3-product emulation: D += Ahi*Bhi + Ahi*Blo + Alo*Bhi.
// ============================================================================
#define MMA16816(d, a, b0, b1)                                               \
    asm volatile("mma.sync.aligned.m16n8k16.row.col.f32.bf16.bf16.f32 "      \
                 "{%0,%1,%2,%3}, {%4,%5,%6,%7}, {%8,%9}, {%0,%1,%2,%3};"     \
                 : "+f"((d)[0]), "+f"((d)[1]), "+f"((d)[2]), "+f"((d)[3])    \
                 : "r"((a)[0]), "r"((a)[1]), "r"((a)[2]), "r"((a)[3]),       \
                   "r"(b0), "r"(b1))

#define KPSTR 18   // u32 stride per smem row (16 kpairs + 2 pad)

__device__ __forceinline__ void split2(float x0, float x1,
                                       uint32_t& hi, uint32_t& lo) {
    __nv_bfloat16 h0 = __float2bfloat16_rn(x0);
    __nv_bfloat16 h1 = __float2bfloat16_rn(x1);
    float r0 = x0 - __bfloat162float(h0);
    float r1 = x1 - __bfloat162float(h1);
    __nv_bfloat16 l0 = __float2bfloat16_rn(r0);
    __nv_bfloat16 l1 = __float2bfloat16_rn(r1);
    hi = (uint32_t)__bfloat16_as_ushort(h0) |
         ((uint32_t)__bfloat16_as_ushort(h1) << 16);
    lo = (uint32_t)__bfloat16_as_ushort(l0) |
         ((uint32_t)__bfloat16_as_ushort(l1) << 16);
}

// ============================================================================
// Unified emulated-bf16 MMA GEMM (validated structure from R5 proj_mma).
// Out[M=8192, N] = A[M,1024] @ W[1024,N] + bias, CTA 128x128, BK=32.
// MODE 0: N=1024, A=g_ao, write Out row-major (output projection).
// MODE 1: N=3072, A=x,    scatter epilogue -> g_q/g_k/g_v [b,h,s,hd].
// ============================================================================
template <int MODE, int NDIM>
__global__ void __launch_bounds__(256) gemm_mma(
    const float* __restrict__ Ain,
    const float* __restrict__ W,      // [K=1024][NDIM] row-major
    const float* __restrict__ bias,   // [NDIM]
    float* __restrict__ Out)
{
    __shared__ uint32_t sAhi[128][KPSTR];
    __shared__ uint32_t sAlo[128][KPSTR];
    __shared__ uint32_t sBhi[128][KPSTR];   // rows = n-local
    __shared__ uint32_t sBlo[128][KPSTR];

    const float* A = (MODE == 0) ? g_ao : Ain;

    const int tid = threadIdx.x;
    const int wid = tid >> 5;
    const int lane = tid & 31;
    const int g = lane >> 2;          // groupID 0..7
    const int t = lane & 3;           // thread-in-group 0..3
    const int wm = wid & 3;           // 32-row slab
    const int wn = wid >> 2;          // 64-col slab
    const int bm = blockIdx.y * 128;
    const int bn = blockIdx.x * 128;

    float acc[2][8][4];
#pragma unroll
    for (int i = 0; i < 2; i++)
#pragma unroll
        for (int j = 0; j < 8; j++)
#pragma unroll
            for (int c = 0; c < 4; c++) acc[i][j][c] = 0.0f;

    for (int kc = 0; kc < 32; kc++) {
        const int k0 = kc * 32;
        // ---- stage A: rows (k contiguous), 128 rows x 16 kpairs ----
#pragma unroll
        for (int i = 0; i < 8; i++) {
            int idx = tid + i * 256;        // 0..2047
            int row = idx >> 4;             // 0..127
            int kp  = idx & 15;             // 0..15
            float2 v = *(const float2*)&A[(size_t)(bm + row) * 1024 + k0 + kp * 2];
            split2(v.x, v.y, sAhi[row][kp], sAlo[row][kp]);
        }
        // ---- stage B: transpose w[k][n] -> smem[n][kpair] ----
#pragma unroll
        for (int i = 0; i < 8; i++) {
            int idx = tid + i * 256;
            int n   = idx & 127;            // coalesced in n
            int kp  = idx >> 7;             // 0..15
            float w0 = W[(size_t)(k0 + kp * 2) * NDIM + bn + n];
            float w1 = W[(size_t)(k0 + kp * 2 + 1) * NDIM + bn + n];
            split2(w0, w1, sBhi[n][kp], sBlo[n][kp]);
        }
        __syncthreads();

#pragma unroll
        for (int ks = 0; ks < 2; ks++) {
            const int kp0 = ks * 8;
            uint32_t ah[2][4], al[2][4];
#pragma unroll
            for (int mt = 0; mt < 2; mt++) {
                int r0 = wm * 32 + mt * 16 + g;
                ah[mt][0] = sAhi[r0][kp0 + t];
                ah[mt][1] = sAhi[r0 + 8][kp0 + t];
                ah[mt][2] = sAhi[r0][kp0 + t + 4];
                ah[mt][3] = sAhi[r0 + 8][kp0 + t + 4];
                al[mt][0] = sAlo[r0][kp0 + t];
                al[mt][1] = sAlo[r0 + 8][kp0 + t];
                al[mt][2] = sAlo[r0][kp0 + t + 4];
                al[mt][3] = sAlo[r0 + 8][kp0 + t + 4];
            }
#pragma unroll
            for (int nt = 0; nt < 8; nt++) {
                int nr = wn * 64 + nt * 8 + g;
                uint32_t bh0 = sBhi[nr][kp0 + t];
                uint32_t bh1 = sBhi[nr][kp0 + t + 4];
                uint32_t bl0 = sBlo[nr][kp0 + t];
                uint32_t bl1 = sBlo[nr][kp0 + t + 4];
#pragma unroll
                for (int mt = 0; mt < 2; mt++) {
                    MMA16816(acc[mt][nt], ah[mt], bh0, bh1);
                    MMA16816(acc[mt][nt], ah[mt], bl0, bl1);
                    MMA16816(acc[mt][nt], al[mt], bh0, bh1);
                }
            }
        }
        __syncthreads();
    }

    // ---- epilogue: d0/d1 -> row g, cols t*2,t*2+1; d2/d3 -> row g+8 ----
#pragma unroll
    for (int mt = 0; mt < 2; mt++) {
        int row0 = bm + wm * 32 + mt * 16 + g;
#pragma unroll
        for (int nt = 0; nt < 8; nt++) {
            int col = bn + wn * 64 + nt * 8 + t * 2;
            float b0 = bias[col], b1 = bias[col + 1];
            float2 v0 = make_float2(acc[mt][nt][0] + b0, acc[mt][nt][1] + b1);
            float2 v1 = make_float2(acc[mt][nt][2] + b0, acc[mt][nt][3] + b1);
            if (MODE == 0) {
                *(float2*)&Out[(size_t)row0 * NDIM + col] = v0;
                *(float2*)&Out[(size_t)(row0 + 8) * NDIM + col] = v1;
            } else {
                int which = col >> 10;
                int h = (col & 1023) >> 6;
                int hd = col & 63;
                float* dst = (which == 0) ? g_q : (which == 1) ? g_k : g_v;
                int b = row0 >> 11, s = row0 & 2047;
                *(float2*)&dst[(((size_t)b * H_ + h) * S_ + s) * HD_ + hd] = v0;
                int r1 = row0 + 8;
                b = r1 >> 11; s = r1 & 2047;
                *(float2*)&dst[(((size_t)b * H_ + h) * S_ + s) * HD_ + hd] = v1;
            }
        }
    }
}

// ============================================================================
// Flash attention, fp32, BQ=BK=64, FULLY PARALLEL in-register online softmax.
// Row state (m, l) lives in registers, replicated across the 16 tx lanes of
// each row group via shuffle reductions. All 256 threads do exp work.
// ============================================================================
#define LD 68
#define FLASH_SMEM_FLOATS (4 * 64 * LD)
#define FLASH_SMEM_BYTES  (FLASH_SMEM_FLOATS * 4)

__global__ void __launch_bounds__(256) flash_kernel()
{
    extern __shared__ float sh[];
    float* Qs = sh;
    float* Ks = Qs + 64 * LD;
    float* Vs = Ks + 64 * LD;
    float* Ss = Vs + 64 * LD;

    const int z  = blockIdx.x;
    const int bh = z >> 5;
    const int qt = 31 - (z & 31);
    const int b  = bh >> 4;
    const int h  = bh & 15;

    const int tid = threadIdx.x;
    const int tx  = tid & 15;
    const int ty  = tid >> 4;

    const float NEG_INF = __int_as_float(0xff800000);

    // Load Q tile (64 x 64)
    {
        const float* qb = g_q + ((size_t)bh * S_ + qt * 64) * HD_;
#pragma unroll
        for (int i = 0; i < 4; i++) {
            int idx = tid + i * 256;
            int row = idx >> 4;
            int c4  = (idx & 15) << 2;
            *(float4*)&Qs[row * LD + c4] = *(const float4*)&qb[row * 64 + c4];
        }
    }

    float m_i[4], l_i[4];
#pragma unroll
    for (int i = 0; i < 4; i++) { m_i[i] = NEG_INF; l_i[i] = 0.0f; }

    float acc[4][4];
#pragma unroll
    for (int i = 0; i < 4; i++)
#pragma unroll
        for (int j = 0; j < 4; j++) acc[i][j] = 0.0f;

    const float scale = 0.125f;

    for (int kt = 0; kt <= qt; kt++) {
        __syncthreads();   // Q ready (iter 0) / prior PV done with Ks,Vs,Ss
        const float* kb = g_k + ((size_t)bh * S_ + kt * 64) * HD_;
        const float* vb = g_v + ((size_t)bh * S_ + kt * 64) * HD_;
#pragma unroll
        for (int i = 0; i < 4; i++) {
            int idx = tid + i * 256;
            int row = idx >> 4;
            int c4  = (idx & 15) << 2;
            *(float4*)&Ks[row * LD + c4] = *(const float4*)&kb[row * 64 + c4];
            *(float4*)&Vs[row * LD + c4] = *(const float4*)&vb[row * 64 + c4];
        }
        __syncthreads();

        // Scores: S = Q K^T * scale (4x4 per thread over k=64)
        float sacc[4][4];
#pragma unroll
        for (int i = 0; i < 4; i++)
#pragma unroll
            for (int j = 0; j < 4; j++) sacc[i][j] = 0.0f;

#pragma unroll
        for (int k = 0; k < 64; k += 4) {
            float4 qa[4], kbf[4];
#pragma unroll
            for (int i = 0; i < 4; i++) qa[i] = *(const float4*)&Qs[(ty * 4 + i) * LD + k];
#pragma unroll
            for (int j = 0; j < 4; j++) kbf[j] = *(const float4*)&Ks[(tx * 4 + j) * LD + k];
#pragma unroll
            for (int i = 0; i < 4; i++)
#pragma unroll
                for (int j = 0; j < 4; j++)
                    sacc[i][j] += qa[i].x * kbf[j].x + qa[i].y * kbf[j].y +
                                  qa[i].z * kbf[j].z + qa[i].w * kbf[j].w;
        }

        // Scale + causal mask in-register
        const bool diag = (kt == qt);
#pragma unroll
        for (int i = 0; i < 4; i++) {
            int r = ty * 4 + i;
#pragma unroll
            for (int j = 0; j < 4; j++) {
                int c = tx * 4 + j;
                float v = sacc[i][j] * scale;
                if (diag && c > r) v = NEG_INF;
                sacc[i][j] = v;
            }
        }

        // Parallel online softmax: shuffle-reduce across the 16 tx lanes.
        float alpha_i[4];
#pragma unroll
        for (int i = 0; i < 4; i++) {
            float rm = fmaxf(fmaxf(sacc[i][0], sacc[i][1]),
                             fmaxf(sacc[i][2], sacc[i][3]));
            rm = fmaxf(rm, __shfl_xor_sync(0xFFFFFFFF, rm, 1));
            rm = fmaxf(rm, __shfl_xor_sync(0xFFFFFFFF, rm, 2));
            rm = fmaxf(rm, __shfl_xor_sync(0xFFFFFFFF, rm, 4));
            rm = fmaxf(rm, __shfl_xor_sync(0xFFFFFFFF, rm, 8));
            float mnew = fmaxf(m_i[i], rm);
            float al = __expf(m_i[i] - mnew);    // 0 when m_i == -inf
            float rs = 0.0f;
#pragma unroll
            for (int j = 0; j < 4; j++) {
                float e = __expf(sacc[i][j] - mnew);
                Ss[(ty * 4 + i) * LD + tx * 4 + j] = e;
                rs += e;
            }
            rs += __shfl_xor_sync(0xFFFFFFFF, rs, 1);
            rs += __shfl_xor_sync(0xFFFFFFFF, rs, 2);
            rs += __shfl_xor_sync(0xFFFFFFFF, rs, 4);
            rs += __shfl_xor_sync(0xFFFFFFFF, rs, 8);
            l_i[i] = l_i[i] * al + rs;
            m_i[i] = mnew;
            alpha_i[i] = al;
        }
        __syncthreads();   // P fully in Ss

        // Rescale accumulators, then O += P V
#pragma unroll
        for (int i = 0; i < 4; i++) {
            float al = alpha_i[i];
#pragma unroll
            for (int j = 0; j < 4; j++) acc[i][j] *= al;
        }
#pragma unroll
        for (int k = 0; k < 64; k += 4) {
            float4 pa[4], vv[4];
#pragma unroll
            for (int i = 0; i < 4; i++) pa[i] = *(const float4*)&Ss[(ty * 4 + i) * LD + k];
#pragma unroll
            for (int kk = 0; kk < 4; kk++) vv[kk] = *(const float4*)&Vs[(k + kk) * LD + tx * 4];
#pragma unroll
            for (int i = 0; i < 4; i++) {
                acc[i][0] += pa[i].x * vv[0].x + pa[i].y * vv[1].x +
                             pa[i].z * vv[2].x + pa[i].w * vv[3].x;
                acc[i][1] += pa[i].x * vv[0].y + pa[i].y * vv[1].y +
                             pa[i].z * vv[2].y + pa[i].w * vv[3].y;
                acc[i][2] += pa[i].x * vv[0].z + pa[i].y * vv[1].z +
                             pa[i].z * vv[2].z + pa[i].w * vv[3].z;
                acc[i][3] += pa[i].x * vv[0].w + pa[i].y * vv[1].w +
                             pa[i].z * vv[2].w + pa[i].w * vv[3].w;
            }
        }
    }

    // Write O / l  ->  g_ao[b*s, h*64 + c]
#pragma unroll
    for (int i = 0; i < 4; i++) {
        int r  = ty * 4 + i;
        int sq = qt * 64 + r;
        float inv = 1.0f / l_i[i];
        float4 o;
        o.x = acc[i][0] * inv; o.y = acc[i][1] * inv;
        o.z = acc[i][2] * inv; o.w = acc[i][3] * inv;
        *(float4*)&g_ao[((size_t)b * S_ + sq) * D_ + h * HD_ + tx * 4] = o;
    }
}

// ============================================================================
// Launch
// ============================================================================
extern "C" void kernel_launch(void* const* d_in, const int* in_sizes, int n_in,
                              void* d_out, int out_size)
{
    const float *x = nullptr, *w_attn = nullptr, *b_attn = nullptr;
    const float *w_proj = nullptr, *b_proj = nullptr;
    for (int i = 0; i < n_in; i++) {
        switch (in_sizes[i]) {
            case 8388608: x      = (const float*)d_in[i]; break;
            case 3145728: w_attn = (const float*)d_in[i]; break;
            case 3072:    b_attn = (const float*)d_in[i]; break;
            case 1048576: w_proj = (const float*)d_in[i]; break;
            case 1024:    b_proj = (const float*)d_in[i]; break;
            default: break;  // mask (ignored; causal handled analytically)
        }
    }
    if (!x)      x      = (const float*)d_in[0];
    if (!w_attn) w_attn = (const float*)d_in[2];
    if (!b_attn) b_attn = (const float*)d_in[3];
    if (!w_proj) w_proj = (const float*)d_in[4];
    if (!b_proj) b_proj = (const float*)d_in[5];

    const int M = B_ * S_;  // 8192

    cudaFuncSetAttribute(flash_kernel, cudaFuncAttributeMaxDynamicSharedMemorySize,
                         FLASH_SMEM_BYTES);

    // 1) QKV projection (emulated-bf16 MMA) with scatter to [b,h,s,hd]
    gemm_mma<1, 3072><<<dim3(3 * D_ / 128, M / 128), 256>>>(
        x, w_attn, b_attn, nullptr);

    // 2) Fused causal flash attention (fp32, parallel softmax)
    flash_kernel<<<B_ * H_ * (S_ / 64), 256, FLASH_SMEM_BYTES>>>();

    // 3) Output projection (emulated-bf16 MMA, validated R5) -> d_out
    gemm_mma<0, 1024><<<dim3(D_ / 128, M / 128), 256>>>(
        nullptr, w_proj, b_proj, (float*)d_out);
}

// round 7
// speedup vs baseline: 2.0451x; 1.6908x over previous
#include <cuda_runtime.h>
#include <cuda_bf16.h>
#include <cstdint>

// Problem constants: B=4, S=2048, D=1024, H=16, HD=64
#define B_ 4
#define H_ 16
#define S_ 2048
#define D_ 1024
#define HD_ 64

// Scratch (allocation-free rule: __device__ globals).
__device__ float g_q[(size_t)B_ * H_ * S_ * HD_];   // [b,h,s,hd]
__device__ float g_k[(size_t)B_ * H_ * S_ * HD_];
__device__ float g_v[(size_t)B_ * H_ * S_ * HD_];
__device__ float g_ao[(size_t)B_ * S_ * D_];        // attention output [b*s, d]

// ============================================================================
// mma.sync m16n8k16 bf16 (baseline PTX; compiles for plain sm_103)
// bf16 2-split 3-product emulation: D += Ahi*Bhi + Ahi*Blo + Alo*Bhi.
// ============================================================================
#define MMA16816(d, a, b0, b1)                                               \
    asm volatile("mma.sync.aligned.m16n8k16.row.col.f32.bf16.bf16.f32 "      \
                 "{%0,%1,%2,%3}, {%4,%5,%6,%7}, {%8,%9}, {%0,%1,%2,%3};"     \
                 : "+f"((d)[0]), "+f"((d)[1]), "+f"((d)[2]), "+f"((d)[3])    \
                 : "r"((a)[0]), "r"((a)[1]), "r"((a)[2]), "r"((a)[3]),       \
                   "r"(b0), "r"(b1))

__device__ __forceinline__ void split2(float x0, float x1,
                                       uint32_t& hi, uint32_t& lo) {
    __nv_bfloat16 h0 = __float2bfloat16_rn(x0);
    __nv_bfloat16 h1 = __float2bfloat16_rn(x1);
    float r0 = x0 - __bfloat162float(h0);
    float r1 = x1 - __bfloat162float(h1);
    __nv_bfloat16 l0 = __float2bfloat16_rn(r0);
    __nv_bfloat16 l1 = __float2bfloat16_rn(r1);
    hi = (uint32_t)__bfloat16_as_ushort(h0) |
         ((uint32_t)__bfloat16_as_ushort(h1) << 16);
    lo = (uint32_t)__bfloat16_as_ushort(l0) |
         ((uint32_t)__bfloat16_as_ushort(l1) << 16);
}

// ============================================================================
// Unified emulated-bf16 MMA GEMM (validated, unchanged from R6).
// ============================================================================
#define KPSTR 18

template <int MODE, int NDIM>
__global__ void __launch_bounds__(256) gemm_mma(
    const float* __restrict__ Ain,
    const float* __restrict__ W,
    const float* __restrict__ bias,
    float* __restrict__ Out)
{
    __shared__ uint32_t sAhi[128][KPSTR];
    __shared__ uint32_t sAlo[128][KPSTR];
    __shared__ uint32_t sBhi[128][KPSTR];
    __shared__ uint32_t sBlo[128][KPSTR];

    const float* A = (MODE == 0) ? g_ao : Ain;

    const int tid = threadIdx.x;
    const int wid = tid >> 5;
    const int lane = tid & 31;
    const int g = lane >> 2;
    const int t = lane & 3;
    const int wm = wid & 3;
    const int wn = wid >> 2;
    const int bm = blockIdx.y * 128;
    const int bn = blockIdx.x * 128;

    float acc[2][8][4];
#pragma unroll
    for (int i = 0; i < 2; i++)
#pragma unroll
        for (int j = 0; j < 8; j++)
#pragma unroll
            for (int c = 0; c < 4; c++) acc[i][j][c] = 0.0f;

    for (int kc = 0; kc < 32; kc++) {
        const int k0 = kc * 32;
#pragma unroll
        for (int i = 0; i < 8; i++) {
            int idx = tid + i * 256;
            int row = idx >> 4;
            int kp  = idx & 15;
            float2 v = *(const float2*)&A[(size_t)(bm + row) * 1024 + k0 + kp * 2];
            split2(v.x, v.y, sAhi[row][kp], sAlo[row][kp]);
        }
#pragma unroll
        for (int i = 0; i < 8; i++) {
            int idx = tid + i * 256;
            int n   = idx & 127;
            int kp  = idx >> 7;
            float w0 = W[(size_t)(k0 + kp * 2) * NDIM + bn + n];
            float w1 = W[(size_t)(k0 + kp * 2 + 1) * NDIM + bn + n];
            split2(w0, w1, sBhi[n][kp], sBlo[n][kp]);
        }
        __syncthreads();

#pragma unroll
        for (int ks = 0; ks < 2; ks++) {
            const int kp0 = ks * 8;
            uint32_t ah[2][4], al[2][4];
#pragma unroll
            for (int mt = 0; mt < 2; mt++) {
                int r0 = wm * 32 + mt * 16 + g;
                ah[mt][0] = sAhi[r0][kp0 + t];
                ah[mt][1] = sAhi[r0 + 8][kp0 + t];
                ah[mt][2] = sAhi[r0][kp0 + t + 4];
                ah[mt][3] = sAhi[r0 + 8][kp0 + t + 4];
                al[mt][0] = sAlo[r0][kp0 + t];
                al[mt][1] = sAlo[r0 + 8][kp0 + t];
                al[mt][2] = sAlo[r0][kp0 + t + 4];
                al[mt][3] = sAlo[r0 + 8][kp0 + t + 4];
            }
#pragma unroll
            for (int nt = 0; nt < 8; nt++) {
                int nr = wn * 64 + nt * 8 + g;
                uint32_t bh0 = sBhi[nr][kp0 + t];
                uint32_t bh1 = sBhi[nr][kp0 + t + 4];
                uint32_t bl0 = sBlo[nr][kp0 + t];
                uint32_t bl1 = sBlo[nr][kp0 + t + 4];
#pragma unroll
                for (int mt = 0; mt < 2; mt++) {
                    MMA16816(acc[mt][nt], ah[mt], bh0, bh1);
                    MMA16816(acc[mt][nt], ah[mt], bl0, bl1);
                    MMA16816(acc[mt][nt], al[mt], bh0, bh1);
                }
            }
        }
        __syncthreads();
    }

#pragma unroll
    for (int mt = 0; mt < 2; mt++) {
        int row0 = bm + wm * 32 + mt * 16 + g;
#pragma unroll
        for (int nt = 0; nt < 8; nt++) {
            int col = bn + wn * 64 + nt * 8 + t * 2;
            float b0 = bias[col], b1 = bias[col + 1];
            float2 v0 = make_float2(acc[mt][nt][0] + b0, acc[mt][nt][1] + b1);
            float2 v1 = make_float2(acc[mt][nt][2] + b0, acc[mt][nt][3] + b1);
            if (MODE == 0) {
                *(float2*)&Out[(size_t)row0 * NDIM + col] = v0;
                *(float2*)&Out[(size_t)(row0 + 8) * NDIM + col] = v1;
            } else {
                int which = col >> 10;
                int h = (col & 1023) >> 6;
                int hd = col & 63;
                float* dst = (which == 0) ? g_q : (which == 1) ? g_k : g_v;
                int b = row0 >> 11, s = row0 & 2047;
                *(float2*)&dst[(((size_t)b * H_ + h) * S_ + s) * HD_ + hd] = v0;
                int r1 = row0 + 8;
                b = r1 >> 11; s = r1 & 2047;
                *(float2*)&dst[(((size_t)b * H_ + h) * S_ + s) * HD_ + hd] = v1;
            }
        }
    }
}

// ============================================================================
// Flash attention on emulated-bf16 HMMA.
// BQ=128, BK=64, 8 warps; warp w owns q-rows [w*16, w*16+16) x full k-width,
// so online softmax is warp-local (shfl over the 4-lane t-group).
// P is re-packed from accumulator registers into A fragments (no smem trip).
// QK^T and PV both use 2-split 3-product emulation.
// ============================================================================
#define KPV 36   // u32 stride: fragment loads hit banks 4g+t -> conflict-free

#define FLASH_SMEM_U32 (2 * 128 * KPV + 4 * 64 * KPV)
#define FLASH_SMEM_BYTES (FLASH_SMEM_U32 * 4)

__global__ void __launch_bounds__(256) flash_mma()
{
    extern __shared__ uint32_t su[];
    uint32_t* sQh = su;
    uint32_t* sQl = sQh + 128 * KPV;
    uint32_t* sKh = sQl + 128 * KPV;
    uint32_t* sKl = sKh + 64 * KPV;
    uint32_t* sVh = sKl + 64 * KPV;
    uint32_t* sVl = sVh + 64 * KPV;

    const int z  = blockIdx.x;
    const int bh = z >> 4;
    const int qt = 15 - (z & 15);          // big tiles first
    const int b  = bh >> 4;
    const int h  = bh & 15;

    const int tid = threadIdx.x;
    const int wid = tid >> 5;
    const int lane = tid & 31;
    const int g = lane >> 2;
    const int t = lane & 3;

    const float NEG_INF = __int_as_float(0xff800000);

    // Stage Q (pre-scaled by 1/sqrt(64)), hi/lo split
    {
        const float* qb = g_q + ((size_t)bh * S_ + qt * 128) * HD_;
#pragma unroll
        for (int i = 0; i < 16; i++) {
            int idx = tid + i * 256;
            int row = idx >> 5, kp = idx & 31;
            float2 v = *(const float2*)&qb[row * 64 + kp * 2];
            uint32_t hi, lo;
            split2(v.x * 0.125f, v.y * 0.125f, hi, lo);
            sQh[row * KPV + kp] = hi;
            sQl[row * KPV + kp] = lo;
        }
    }

    float m0 = NEG_INF, m1 = NEG_INF, l0 = 0.0f, l1 = 0.0f;
    float acco[8][4];
#pragma unroll
    for (int nt = 0; nt < 8; nt++)
#pragma unroll
        for (int c = 0; c < 4; c++) acco[nt][c] = 0.0f;

    const int ktmax = 2 * qt + 1;
    const int rg0 = qt * 128 + wid * 16 + g;   // global q-row of d0/d1
    const int warp_row_hi = qt * 128 + wid * 16 + 15;

    for (int kt = 0; kt <= ktmax; kt++) {
        __syncthreads();   // protect K/V smem from previous iteration's PV
        const float* kbp = g_k + ((size_t)bh * S_ + kt * 64) * HD_;
        const float* vbp = g_v + ((size_t)bh * S_ + kt * 64) * HD_;
#pragma unroll
        for (int i = 0; i < 8; i++) {
            int idx = tid + i * 256;
            int row = idx >> 5, kp = idx & 31;
            float2 v = *(const float2*)&kbp[row * 64 + kp * 2];
            uint32_t hi, lo;
            split2(v.x, v.y, hi, lo);
            sKh[row * KPV + kp] = hi;
            sKl[row * KPV + kp] = lo;
        }
        // V transposed: smem[hd][seq-pair]
#pragma unroll
        for (int i = 0; i < 8; i++) {
            int idx = tid + i * 256;
            int hd = idx & 63, sp = idx >> 6;
            float v0 = vbp[(size_t)(sp * 2) * 64 + hd];
            float v1 = vbp[(size_t)(sp * 2 + 1) * 64 + hd];
            uint32_t hi, lo;
            split2(v0, v1, hi, lo);
            sVh[hd * KPV + sp] = hi;
            sVl[hd * KPV + sp] = lo;
        }
        __syncthreads();

        if (warp_row_hi < kt * 64) continue;  // warp fully below this k-tile

        // ---- QK^T (emulated) ----
        float accs[8][4];
#pragma unroll
        for (int nt = 0; nt < 8; nt++)
#pragma unroll
            for (int c = 0; c < 4; c++) accs[nt][c] = 0.0f;

#pragma unroll
        for (int ks = 0; ks < 4; ks++) {
            const int r0s = (wid * 16 + g) * KPV;
            const int kpb = ks * 8 + t;
            uint32_t ah[4] = { sQh[r0s + kpb],          sQh[r0s + 8 * KPV + kpb],
                               sQh[r0s + kpb + 4],      sQh[r0s + 8 * KPV + kpb + 4] };
            uint32_t al[4] = { sQl[r0s + kpb],          sQl[r0s + 8 * KPV + kpb],
                               sQl[r0s + kpb + 4],      sQl[r0s + 8 * KPV + kpb + 4] };
#pragma unroll
            for (int nt = 0; nt < 8; nt++) {
                int nr = (nt * 8 + g) * KPV;
                uint32_t bh0 = sKh[nr + kpb], bh1 = sKh[nr + kpb + 4];
                uint32_t bl0 = sKl[nr + kpb], bl1 = sKl[nr + kpb + 4];
                MMA16816(accs[nt], ah, bh0, bh1);
                MMA16816(accs[nt], ah, bl0, bl1);
                MMA16816(accs[nt], al, bh0, bh1);
            }
        }

        // ---- causal mask (only possible on the last two k-tiles) ----
        if (kt >= 2 * qt) {
            const int rg1 = rg0 + 8;
#pragma unroll
            for (int nt = 0; nt < 8; nt++) {
                int c0 = kt * 64 + nt * 8 + t * 2;
                int c1 = c0 + 1;
                if (c0 > rg0) accs[nt][0] = NEG_INF;
                if (c1 > rg0) accs[nt][1] = NEG_INF;
                if (c0 > rg1) accs[nt][2] = NEG_INF;
                if (c1 > rg1) accs[nt][3] = NEG_INF;
            }
        }

        // ---- warp-local online softmax ----
        float rm0 = NEG_INF, rm1 = NEG_INF;
#pragma unroll
        for (int nt = 0; nt < 8; nt++) {
            rm0 = fmaxf(rm0, fmaxf(accs[nt][0], accs[nt][1]));
            rm1 = fmaxf(rm1, fmaxf(accs[nt][2], accs[nt][3]));
        }
        rm0 = fmaxf(rm0, __shfl_xor_sync(0xFFFFFFFF, rm0, 1));
        rm0 = fmaxf(rm0, __shfl_xor_sync(0xFFFFFFFF, rm0, 2));
        rm1 = fmaxf(rm1, __shfl_xor_sync(0xFFFFFFFF, rm1, 1));
        rm1 = fmaxf(rm1, __shfl_xor_sync(0xFFFFFFFF, rm1, 2));

        float mn0 = fmaxf(m0, rm0), mn1 = fmaxf(m1, rm1);
        float a0 = __expf(m0 - mn0);   // 0 when m0 == -inf
        float a1 = __expf(m1 - mn1);

        // exp + P fragment packing (accumulator layout == A-operand layout)
        uint32_t pah[4][4], pal[4][4];
        float rs0 = 0.0f, rs1 = 0.0f;
#pragma unroll
        for (int nt = 0; nt < 8; nt++) {
            float p0 = __expf(accs[nt][0] - mn0);
            float p1 = __expf(accs[nt][1] - mn0);
            float p2 = __expf(accs[nt][2] - mn1);
            float p3 = __expf(accs[nt][3] - mn1);
            rs0 += p0 + p1;
            rs1 += p2 + p3;
            uint32_t h01, l01, h23, l23;
            split2(p0, p1, h01, l01);
            split2(p2, p3, h23, l23);
            int ks = nt >> 1, half = nt & 1;
            pah[ks][half * 2]     = h01;
            pah[ks][half * 2 + 1] = h23;
            pal[ks][half * 2]     = l01;
            pal[ks][half * 2 + 1] = l23;
        }
        rs0 += __shfl_xor_sync(0xFFFFFFFF, rs0, 1);
        rs0 += __shfl_xor_sync(0xFFFFFFFF, rs0, 2);
        rs1 += __shfl_xor_sync(0xFFFFFFFF, rs1, 1);
        rs1 += __shfl_xor_sync(0xFFFFFFFF, rs1, 2);

        l0 = l0 * a0 + rs0;
        l1 = l1 * a1 + rs1;
        m0 = mn0;
        m1 = mn1;

        // rescale O accumulators
#pragma unroll
        for (int nt = 0; nt < 8; nt++) {
            acco[nt][0] *= a0; acco[nt][1] *= a0;
            acco[nt][2] *= a1; acco[nt][3] *= a1;
        }

        // ---- PV (emulated; P from registers, V^T from smem) ----
#pragma unroll
        for (int ks = 0; ks < 4; ks++) {
            const int kpb = ks * 8 + t;
#pragma unroll
            for (int nt = 0; nt < 8; nt++) {
                int nr = (nt * 8 + g) * KPV;
                uint32_t bh0 = sVh[nr + kpb], bh1 = sVh[nr + kpb + 4];
                uint32_t bl0 = sVl[nr + kpb], bl1 = sVl[nr + kpb + 4];
                MMA16816(acco[nt], pah[ks], bh0, bh1);
                MMA16816(acco[nt], pal[ks], bh0, bh1);
                MMA16816(acco[nt], pah[ks], bl0, bl1);
            }
        }
    }

    // ---- epilogue: O / l -> g_ao[b*s][h*64 + c] ----
    const float i0 = 1.0f / l0;
    const float i1 = 1.0f / l1;
    const int sq = qt * 128 + wid * 16 + g;
#pragma unroll
    for (int nt = 0; nt < 8; nt++) {
        int col = h * 64 + nt * 8 + t * 2;
        float2 v0 = make_float2(acco[nt][0] * i0, acco[nt][1] * i0);
        float2 v1 = make_float2(acco[nt][2] * i1, acco[nt][3] * i1);
        *(float2*)&g_ao[((size_t)b * S_ + sq) * D_ + col] = v0;
        *(float2*)&g_ao[((size_t)b * S_ + sq + 8) * D_ + col] = v1;
    }
}

// ============================================================================
// Launch
// ============================================================================
extern "C" void kernel_launch(void* const* d_in, const int* in_sizes, int n_in,
                              void* d_out, int out_size)
{
    const float *x = nullptr, *w_attn = nullptr, *b_attn = nullptr;
    const float *w_proj = nullptr, *b_proj = nullptr;
    for (int i = 0; i < n_in; i++) {
        switch (in_sizes[i]) {
            case 8388608: x      = (const float*)d_in[i]; break;
            case 3145728: w_attn = (const float*)d_in[i]; break;
            case 3072:    b_attn = (const float*)d_in[i]; break;
            case 1048576: w_proj = (const float*)d_in[i]; break;
            case 1024:    b_proj = (const float*)d_in[i]; break;
            default: break;  // mask (ignored; causal handled analytically)
        }
    }
    if (!x)      x      = (const float*)d_in[0];
    if (!w_attn) w_attn = (const float*)d_in[2];
    if (!b_attn) b_attn = (const float*)d_in[3];
    if (!w_proj) w_proj = (const float*)d_in[4];
    if (!b_proj) b_proj = (const float*)d_in[5];

    const int M = B_ * S_;  // 8192

    cudaFuncSetAttribute(flash_mma, cudaFuncAttributeMaxDynamicSharedMemorySize,
                         FLASH_SMEM_BYTES);

    // 1) QKV projection (emulated-bf16 MMA) with scatter to [b,h,s,hd]
    gemm_mma<1, 3072><<<dim3(3 * D_ / 128, M / 128), 256>>>(
        x, w_attn, b_attn, nullptr);

    // 2) Fused causal flash attention (emulated-bf16 MMA)
    flash_mma<<<B_ * H_ * (S_ / 128), 256, FLASH_SMEM_BYTES>>>();

    // 3) Output projection (emulated-bf16 MMA) -> d_out
    gemm_mma<0, 1024><<<dim3(D_ / 128, M / 128), 256>>>(
        nullptr, w_proj, b_proj, (float*)d_out);
}

// round 8
// speedup vs baseline: 2.4565x; 1.2012x over previous
#include <cuda_runtime.h>
#include <cuda_bf16.h>
#include <cstdint>

// Problem constants: B=4, S=2048, D=1024, H=16, HD=64
#define B_ 4
#define H_ 16
#define S_ 2048
#define D_ 1024
#define HD_ 64

// Scratch (allocation-free rule: __device__ globals).
__device__ float g_q[(size_t)B_ * H_ * S_ * HD_];   // [b,h,s,hd]
__device__ float g_k[(size_t)B_ * H_ * S_ * HD_];
__device__ float g_v[(size_t)B_ * H_ * S_ * HD_];
__device__ float g_ao[(size_t)B_ * S_ * D_];        // attention output [b*s, d]

// ============================================================================
// mma.sync m16n8k16 bf16 (baseline PTX; compiles for plain sm_103)
// bf16 2-split 3-product emulation: D += Ahi*Bhi + Ahi*Blo + Alo*Bhi.
// ============================================================================
#define MMA16816(d, a, b0, b1)                                               \
    asm volatile("mma.sync.aligned.m16n8k16.row.col.f32.bf16.bf16.f32 "      \
                 "{%0,%1,%2,%3}, {%4,%5,%6,%7}, {%8,%9}, {%0,%1,%2,%3};"     \
                 : "+f"((d)[0]), "+f"((d)[1]), "+f"((d)[2]), "+f"((d)[3])    \
                 : "r"((a)[0]), "r"((a)[1]), "r"((a)[2]), "r"((a)[3]),       \
                   "r"(b0), "r"(b1))

__device__ __forceinline__ void split2(float x0, float x1,
                                       uint32_t& hi, uint32_t& lo) {
    __nv_bfloat16 h0 = __float2bfloat16_rn(x0);
    __nv_bfloat16 h1 = __float2bfloat16_rn(x1);
    float r0 = x0 - __bfloat162float(h0);
    float r1 = x1 - __bfloat162float(h1);
    __nv_bfloat16 l0 = __float2bfloat16_rn(r0);
    __nv_bfloat16 l1 = __float2bfloat16_rn(r1);
    hi = (uint32_t)__bfloat16_as_ushort(h0) |
         ((uint32_t)__bfloat16_as_ushort(h1) << 16);
    lo = (uint32_t)__bfloat16_as_ushort(l0) |
         ((uint32_t)__bfloat16_as_ushort(l1) << 16);
}

// ============================================================================
// Double-buffered emulated-bf16 MMA GEMM.
// Out[M=8192, N] = A[M,1024] @ W[1024,N] + bias, CTA 128x128, BK=32.
// Pipeline: LDG(kc+1) -> MMA(kc) -> convert/store(kc+1) -> sync.
// MODE 0: N=1024, A=g_ao, row-major Out. MODE 1: N=3072, scatter q/k/v.
// ============================================================================
#define KPSTR 18
#define GTILE (128 * KPSTR)            // u32 per sub-array (2304)
#define GBUF  (4 * GTILE)              // u32 per buffer (Ahi,Alo,Bhi,Blo)
#define GEMM_SMEM_BYTES (2 * GBUF * 4) // 73728

template <int MODE, int NDIM>
__global__ void __launch_bounds__(256) gemm_mma(
    const float* __restrict__ Ain,
    const float* __restrict__ W,
    const float* __restrict__ bias,
    float* __restrict__ Out)
{
    extern __shared__ uint32_t dsm[];

    const float* A = (MODE == 0) ? g_ao : Ain;

    const int tid = threadIdx.x;
    const int wid = tid >> 5;
    const int lane = tid & 31;
    const int g = lane >> 2;
    const int t = lane & 3;
    const int wm = wid & 3;
    const int wn = wid >> 2;
    const int bm = blockIdx.y * 128;
    const int bn = blockIdx.x * 128;

    // per-thread staging coords
    const int arow = tid >> 4,  akp = tid & 15;    // A: +row stride 16/iter
    const int bn_l = tid & 127, bkp = tid >> 7;    // B: +kp stride 2/iter

    float acc[2][8][4];
#pragma unroll
    for (int i = 0; i < 2; i++)
#pragma unroll
        for (int j = 0; j < 8; j++)
#pragma unroll
            for (int c = 0; c < 4; c++) acc[i][j][c] = 0.0f;

    // ---- prologue: stage tile 0 into buffer 0 ----
    {
        uint32_t* pAh = dsm;
        uint32_t* pAl = pAh + GTILE;
        uint32_t* pBh = pAl + GTILE;
        uint32_t* pBl = pBh + GTILE;
#pragma unroll
        for (int i = 0; i < 8; i++) {
            int row = arow + i * 16;
            float2 v = *(const float2*)&A[(size_t)(bm + row) * 1024 + akp * 2];
            split2(v.x, v.y, pAh[row * KPSTR + akp], pAl[row * KPSTR + akp]);
        }
#pragma unroll
        for (int i = 0; i < 8; i++) {
            int kp = bkp + i * 2;
            float w0 = W[(size_t)(kp * 2) * NDIM + bn + bn_l];
            float w1 = W[(size_t)(kp * 2 + 1) * NDIM + bn + bn_l];
            split2(w0, w1, pBh[bn_l * KPSTR + kp], pBl[bn_l * KPSTR + kp]);
        }
    }
    __syncthreads();

    float2 ra[8];
    float rb0[8], rb1[8];

    for (int kc = 0; kc < 32; kc++) {
        const int cur = kc & 1;
        const int nxt = cur ^ 1;
        const bool more = (kc + 1 < 32);

        // ---- issue next tile's global loads (latency hidden by MMAs) ----
        if (more) {
            const int k1 = (kc + 1) * 32;
#pragma unroll
            for (int i = 0; i < 8; i++) {
                int row = arow + i * 16;
                ra[i] = *(const float2*)&A[(size_t)(bm + row) * 1024 + k1 + akp * 2];
            }
#pragma unroll
            for (int i = 0; i < 8; i++) {
                int kp = bkp + i * 2;
                rb0[i] = W[(size_t)(k1 + kp * 2) * NDIM + bn + bn_l];
                rb1[i] = W[(size_t)(k1 + kp * 2 + 1) * NDIM + bn + bn_l];
            }
        }

        // ---- MMAs on current buffer ----
        {
            const uint32_t* pAh = dsm + cur * GBUF;
            const uint32_t* pAl = pAh + GTILE;
            const uint32_t* pBh = pAl + GTILE;
            const uint32_t* pBl = pBh + GTILE;
#pragma unroll
            for (int ks = 0; ks < 2; ks++) {
                const int kp0 = ks * 8;
                uint32_t ah[2][4], al[2][4];
#pragma unroll
                for (int mt = 0; mt < 2; mt++) {
                    int r0 = (wm * 32 + mt * 16 + g) * KPSTR;
                    ah[mt][0] = pAh[r0 + kp0 + t];
                    ah[mt][1] = pAh[r0 + 8 * KPSTR + kp0 + t];
                    ah[mt][2] = pAh[r0 + kp0 + t + 4];
                    ah[mt][3] = pAh[r0 + 8 * KPSTR + kp0 + t + 4];
                    al[mt][0] = pAl[r0 + kp0 + t];
                    al[mt][1] = pAl[r0 + 8 * KPSTR + kp0 + t];
                    al[mt][2] = pAl[r0 + kp0 + t + 4];
                    al[mt][3] = pAl[r0 + 8 * KPSTR + kp0 + t + 4];
                }
#pragma unroll
                for (int nt = 0; nt < 8; nt++) {
                    int nr = (wn * 64 + nt * 8 + g) * KPSTR;
                    uint32_t bh0 = pBh[nr + kp0 + t];
                    uint32_t bh1 = pBh[nr + kp0 + t + 4];
                    uint32_t bl0 = pBl[nr + kp0 + t];
                    uint32_t bl1 = pBl[nr + kp0 + t + 4];
#pragma unroll
                    for (int mt = 0; mt < 2; mt++) {
                        MMA16816(acc[mt][nt], ah[mt], bh0, bh1);
                        MMA16816(acc[mt][nt], ah[mt], bl0, bl1);
                        MMA16816(acc[mt][nt], al[mt], bh0, bh1);
                    }
                }
            }
        }

        // ---- convert + store next tile ----
        if (more) {
            uint32_t* pAh = dsm + nxt * GBUF;
            uint32_t* pAl = pAh + GTILE;
            uint32_t* pBh = pAl + GTILE;
            uint32_t* pBl = pBh + GTILE;
#pragma unroll
            for (int i = 0; i < 8; i++) {
                int row = arow + i * 16;
                split2(ra[i].x, ra[i].y,
                       pAh[row * KPSTR + akp], pAl[row * KPSTR + akp]);
            }
#pragma unroll
            for (int i = 0; i < 8; i++) {
                int kp = bkp + i * 2;
                split2(rb0[i], rb1[i],
                       pBh[bn_l * KPSTR + kp], pBl[bn_l * KPSTR + kp]);
            }
        }
        __syncthreads();
    }

    // ---- epilogue ----
#pragma unroll
    for (int mt = 0; mt < 2; mt++) {
        int row0 = bm + wm * 32 + mt * 16 + g;
#pragma unroll
        for (int nt = 0; nt < 8; nt++) {
            int col = bn + wn * 64 + nt * 8 + t * 2;
            float b0 = bias[col], b1 = bias[col + 1];
            float2 v0 = make_float2(acc[mt][nt][0] + b0, acc[mt][nt][1] + b1);
            float2 v1 = make_float2(acc[mt][nt][2] + b0, acc[mt][nt][3] + b1);
            if (MODE == 0) {
                *(float2*)&Out[(size_t)row0 * NDIM + col] = v0;
                *(float2*)&Out[(size_t)(row0 + 8) * NDIM + col] = v1;
            } else {
                int which = col >> 10;
                int h = (col & 1023) >> 6;
                int hd = col & 63;
                float* dst = (which == 0) ? g_q : (which == 1) ? g_k : g_v;
                int b = row0 >> 11, s = row0 & 2047;
                *(float2*)&dst[(((size_t)b * H_ + h) * S_ + s) * HD_ + hd] = v0;
                int r1 = row0 + 8;
                b = r1 >> 11; s = r1 & 2047;
                *(float2*)&dst[(((size_t)b * H_ + h) * S_ + s) * HD_ + hd] = v1;
            }
        }
    }
}

// ============================================================================
// Flash attention on emulated-bf16 HMMA, double-buffered K/V pipeline.
// BQ=128, BK=64, 8 warps; softmax warp-local; P packed reg->fragment.
// ============================================================================
#define KPV 36
#define QTILE (128 * KPV)              // u32 (4608)
#define KVTILE (64 * KPV)              // u32 per sub-array (2304)
#define KVBUF (4 * KVTILE)             // Kh,Kl,Vh,Vl per buffer (9216)
#define FLASH_SMEM_BYTES ((2 * QTILE + 2 * KVBUF) * 4)   // 110592

__global__ void __launch_bounds__(256) flash_mma()
{
    extern __shared__ uint32_t su[];
    uint32_t* sQh = su;                      // [128][KPV]
    uint32_t* sQl = sQh + QTILE;
    uint32_t* kvbase = sQl + QTILE;          // 2 buffers of (Kh,Kl,Vh,Vl)

    const int z  = blockIdx.x;
    const int bh = z >> 4;
    const int qt = 15 - (z & 15);            // big tiles first
    const int b  = bh >> 4;
    const int h  = bh & 15;

    const int tid = threadIdx.x;
    const int wid = tid >> 5;
    const int lane = tid & 31;
    const int g = lane >> 2;
    const int t = lane & 3;

    const float NEG_INF = __int_as_float(0xff800000);

    const float* kbase = g_k + (size_t)bh * S_ * HD_;
    const float* vbase = g_v + (size_t)bh * S_ * HD_;

    // staging coords
    const int krow = tid >> 3, kkp = (tid & 7) * 4;    // K: 32 rows/iter... (see below)
    // K: idx = tid + i*256, row = idx>>5 (8 iters covers 64 rows? 2048 idx / 32 = 64 rows) keep orig
    // V: hd = idx&63, sp = idx>>6

    // ---- stage Q (pre-scaled), single buffer ----
    {
        const float* qb = g_q + ((size_t)bh * S_ + qt * 128) * HD_;
#pragma unroll
        for (int i = 0; i < 16; i++) {
            int idx = tid + i * 256;
            int row = idx >> 5, kp = idx & 31;
            float2 v = *(const float2*)&qb[row * 64 + kp * 2];
            split2(v.x * 0.125f, v.y * 0.125f,
                   sQh[row * KPV + kp], sQl[row * KPV + kp]);
        }
    }

    float m0 = NEG_INF, m1 = NEG_INF, l0 = 0.0f, l1 = 0.0f;
    float acco[8][4];
#pragma unroll
    for (int nt = 0; nt < 8; nt++)
#pragma unroll
        for (int c = 0; c < 4; c++) acco[nt][c] = 0.0f;

    const int ktmax = 2 * qt + 1;
    const int rg0 = qt * 128 + wid * 16 + g;
    const int warp_row_hi = qt * 128 + wid * 16 + 15;

    // ---- prologue: stage K/V tile 0 into buffer 0 ----
    {
        uint32_t* pKh = kvbase;
        uint32_t* pKl = pKh + KVTILE;
        uint32_t* pVh = pKl + KVTILE;
        uint32_t* pVl = pVh + KVTILE;
#pragma unroll
        for (int i = 0; i < 8; i++) {
            int idx = tid + i * 256;
            int row = idx >> 5, kp = idx & 31;
            float2 v = *(const float2*)&kbase[(size_t)row * 64 + kp * 2];
            split2(v.x, v.y, pKh[row * KPV + kp], pKl[row * KPV + kp]);
        }
#pragma unroll
        for (int i = 0; i < 8; i++) {
            int idx = tid + i * 256;
            int hd = idx & 63, sp = idx >> 6;
            float v0 = vbase[(size_t)(sp * 2) * 64 + hd];
            float v1 = vbase[(size_t)(sp * 2 + 1) * 64 + hd];
            split2(v0, v1, pVh[hd * KPV + sp], pVl[hd * KPV + sp]);
        }
    }
    __syncthreads();

    float2 rk[8];
    float rv0[8], rv1[8];

    for (int kt = 0; kt <= ktmax; kt++) {
        const int cur = kt & 1;
        const int nxt = cur ^ 1;
        const bool more = (kt < ktmax);

        // ---- issue next K/V tile's global loads ----
        if (more) {
            const float* kbp = kbase + (size_t)(kt + 1) * 64 * HD_;
            const float* vbp = vbase + (size_t)(kt + 1) * 64 * HD_;
#pragma unroll
            for (int i = 0; i < 8; i++) {
                int idx = tid + i * 256;
                int row = idx >> 5, kp = idx & 31;
                rk[i] = *(const float2*)&kbp[(size_t)row * 64 + kp * 2];
            }
#pragma unroll
            for (int i = 0; i < 8; i++) {
                int idx = tid + i * 256;
                int hd = idx & 63, sp = idx >> 6;
                rv0[i] = vbp[(size_t)(sp * 2) * 64 + hd];
                rv1[i] = vbp[(size_t)(sp * 2 + 1) * 64 + hd];
            }
        }

        // ---- compute on current buffer (warps above the causal line only) ----
        if (warp_row_hi >= kt * 64) {
            const uint32_t* pKh = kvbase + cur * KVBUF;
            const uint32_t* pKl = pKh + KVTILE;
            const uint32_t* pVh = pKl + KVTILE;
            const uint32_t* pVl = pVh + KVTILE;

            // QK^T
            float accs[8][4];
#pragma unroll
            for (int nt = 0; nt < 8; nt++)
#pragma unroll
                for (int c = 0; c < 4; c++) accs[nt][c] = 0.0f;

#pragma unroll
            for (int ks = 0; ks < 4; ks++) {
                const int r0s = (wid * 16 + g) * KPV;
                const int kpb = ks * 8 + t;
                uint32_t ah[4] = { sQh[r0s + kpb],     sQh[r0s + 8 * KPV + kpb],
                                   sQh[r0s + kpb + 4], sQh[r0s + 8 * KPV + kpb + 4] };
                uint32_t al[4] = { sQl[r0s + kpb],     sQl[r0s + 8 * KPV + kpb],
                                   sQl[r0s + kpb + 4], sQl[r0s + 8 * KPV + kpb + 4] };
#pragma unroll
                for (int nt = 0; nt < 8; nt++) {
                    int nr = (nt * 8 + g) * KPV;
                    uint32_t bh0 = pKh[nr + kpb], bh1 = pKh[nr + kpb + 4];
                    uint32_t bl0 = pKl[nr + kpb], bl1 = pKl[nr + kpb + 4];
                    MMA16816(accs[nt], ah, bh0, bh1);
                    MMA16816(accs[nt], ah, bl0, bl1);
                    MMA16816(accs[nt], al, bh0, bh1);
                }
            }

            // causal mask
            if (kt >= 2 * qt) {
                const int rg1 = rg0 + 8;
#pragma unroll
                for (int nt = 0; nt < 8; nt++) {
                    int c0 = kt * 64 + nt * 8 + t * 2;
                    int c1 = c0 + 1;
                    if (c0 > rg0) accs[nt][0] = NEG_INF;
                    if (c1 > rg0) accs[nt][1] = NEG_INF;
                    if (c0 > rg1) accs[nt][2] = NEG_INF;
                    if (c1 > rg1) accs[nt][3] = NEG_INF;
                }
            }

            // warp-local online softmax
            float rm0 = NEG_INF, rm1 = NEG_INF;
#pragma unroll
            for (int nt = 0; nt < 8; nt++) {
                rm0 = fmaxf(rm0, fmaxf(accs[nt][0], accs[nt][1]));
                rm1 = fmaxf(rm1, fmaxf(accs[nt][2], accs[nt][3]));
            }
            rm0 = fmaxf(rm0, __shfl_xor_sync(0xFFFFFFFF, rm0, 1));
            rm0 = fmaxf(rm0, __shfl_xor_sync(0xFFFFFFFF, rm0, 2));
            rm1 = fmaxf(rm1, __shfl_xor_sync(0xFFFFFFFF, rm1, 1));
            rm1 = fmaxf(rm1, __shfl_xor_sync(0xFFFFFFFF, rm1, 2));

            float mn0 = fmaxf(m0, rm0), mn1 = fmaxf(m1, rm1);
            float a0 = __expf(m0 - mn0);
            float a1 = __expf(m1 - mn1);

            uint32_t pah[4][4], pal[4][4];
            float rs0 = 0.0f, rs1 = 0.0f;
#pragma unroll
            for (int nt = 0; nt < 8; nt++) {
                float p0 = __expf(accs[nt][0] - mn0);
                float p1 = __expf(accs[nt][1] - mn0);
                float p2 = __expf(accs[nt][2] - mn1);
                float p3 = __expf(accs[nt][3] - mn1);
                rs0 += p0 + p1;
                rs1 += p2 + p3;
                uint32_t h01, l01, h23, l23;
                split2(p0, p1, h01, l01);
                split2(p2, p3, h23, l23);
                int ks = nt >> 1, half = nt & 1;
                pah[ks][half * 2]     = h01;
                pah[ks][half * 2 + 1] = h23;
                pal[ks][half * 2]     = l01;
                pal[ks][half * 2 + 1] = l23;
            }
            rs0 += __shfl_xor_sync(0xFFFFFFFF, rs0, 1);
            rs0 += __shfl_xor_sync(0xFFFFFFFF, rs0, 2);
            rs1 += __shfl_xor_sync(0xFFFFFFFF, rs1, 1);
            rs1 += __shfl_xor_sync(0xFFFFFFFF, rs1, 2);

            l0 = l0 * a0 + rs0;
            l1 = l1 * a1 + rs1;
            m0 = mn0;
            m1 = mn1;

#pragma unroll
            for (int nt = 0; nt < 8; nt++) {
                acco[nt][0] *= a0; acco[nt][1] *= a0;
                acco[nt][2] *= a1; acco[nt][3] *= a1;
            }

            // PV
#pragma unroll
            for (int ks = 0; ks < 4; ks++) {
                const int kpb = ks * 8 + t;
#pragma unroll
                for (int nt = 0; nt < 8; nt++) {
                    int nr = (nt * 8 + g) * KPV;
                    uint32_t bh0 = pVh[nr + kpb], bh1 = pVh[nr + kpb + 4];
                    uint32_t bl0 = pVl[nr + kpb], bl1 = pVl[nr + kpb + 4];
                    MMA16816(acco[nt], pah[ks], bh0, bh1);
                    MMA16816(acco[nt], pal[ks], bh0, bh1);
                    MMA16816(acco[nt], pah[ks], bl0, bl1);
                }
            }
        }

        // ---- convert + store next K/V tile ----
        if (more) {
            uint32_t* pKh = kvbase + nxt * KVBUF;
            uint32_t* pKl = pKh + KVTILE;
            uint32_t* pVh = pKl + KVTILE;
            uint32_t* pVl = pVh + KVTILE;
#pragma unroll
            for (int i = 0; i < 8; i++) {
                int idx = tid + i * 256;
                int row = idx >> 5, kp = idx & 31;
                split2(rk[i].x, rk[i].y,
                       pKh[row * KPV + kp], pKl[row * KPV + kp]);
            }
#pragma unroll
            for (int i = 0; i < 8; i++) {
                int idx = tid + i * 256;
                int hd = idx & 63, sp = idx >> 6;
                split2(rv0[i], rv1[i],
                       pVh[hd * KPV + sp], pVl[hd * KPV + sp]);
            }
        }
        __syncthreads();
    }

    // ---- epilogue: O / l -> g_ao[b*s][h*64 + c] ----
    const float i0 = 1.0f / l0;
    const float i1 = 1.0f / l1;
    const int sq = qt * 128 + wid * 16 + g;
#pragma unroll
    for (int nt = 0; nt < 8; nt++) {
        int col = h * 64 + nt * 8 + t * 2;
        float2 v0 = make_float2(acco[nt][0] * i0, acco[nt][1] * i0);
        float2 v1 = make_float2(acco[nt][2] * i1, acco[nt][3] * i1);
        *(float2*)&g_ao[((size_t)b * S_ + sq) * D_ + col] = v0;
        *(float2*)&g_ao[((size_t)b * S_ + sq + 8) * D_ + col] = v1;
    }
}

// ============================================================================
// Launch
// ============================================================================
extern "C" void kernel_launch(void* const* d_in, const int* in_sizes, int n_in,
                              void* d_out, int out_size)
{
    const float *x = nullptr, *w_attn = nullptr, *b_attn = nullptr;
    const float *w_proj = nullptr, *b_proj = nullptr;
    for (int i = 0; i < n_in; i++) {
        switch (in_sizes[i]) {
            case 8388608: x      = (const float*)d_in[i]; break;
            case 3145728: w_attn = (const float*)d_in[i]; break;
            case 3072:    b_attn = (const float*)d_in[i]; break;
            case 1048576: w_proj = (const float*)d_in[i]; break;
            case 1024:    b_proj = (const float*)d_in[i]; break;
            default: break;  // mask (ignored; causal handled analytically)
        }
    }
    if (!x)      x      = (const float*)d_in[0];
    if (!w_attn) w_attn = (const float*)d_in[2];
    if (!b_attn) b_attn = (const float*)d_in[3];
    if (!w_proj) w_proj = (const float*)d_in[4];
    if (!b_proj) b_proj = (const float*)d_in[5];

    const int M = B_ * S_;  // 8192

    cudaFuncSetAttribute(gemm_mma<1, 3072>,
                         cudaFuncAttributeMaxDynamicSharedMemorySize,
                         GEMM_SMEM_BYTES);
    cudaFuncSetAttribute(gemm_mma<0, 1024>,
                         cudaFuncAttributeMaxDynamicSharedMemorySize,
                         GEMM_SMEM_BYTES);
    cudaFuncSetAttribute(flash_mma,
                         cudaFuncAttributeMaxDynamicSharedMemorySize,
                         FLASH_SMEM_BYTES);

    // 1) QKV projection (pipelined emulated-bf16 MMA), scatter to [b,h,s,hd]
    gemm_mma<1, 3072><<<dim3(3 * D_ / 128, M / 128), 256, GEMM_SMEM_BYTES>>>(
        x, w_attn, b_attn, nullptr);

    // 2) Fused causal flash attention (pipelined emulated-bf16 MMA)
    flash_mma<<<B_ * H_ * (S_ / 128), 256, FLASH_SMEM_BYTES>>>();

    // 3) Output projection (pipelined emulated-bf16 MMA) -> d_out
    gemm_mma<0, 1024><<<dim3(D_ / 128, M / 128), 256, GEMM_SMEM_BYTES>>>(
        nullptr, w_proj, b_proj, (float*)d_out);
}

// round 9
// speedup vs baseline: 2.4684x; 1.0049x over previous
#include <cuda_runtime.h>
#include <cuda_bf16.h>
#include <cstdint>

// Problem constants: B=4, S=2048, D=1024, H=16, HD=64
#define B_ 4
#define H_ 16
#define S_ 2048
#define D_ 1024
#define HD_ 64

// Scratch (allocation-free rule: __device__ globals).
__device__ float g_q[(size_t)B_ * H_ * S_ * HD_];   // [b,h,s,hd]
__device__ float g_k[(size_t)B_ * H_ * S_ * HD_];
__device__ float g_v[(size_t)B_ * H_ * S_ * HD_];
__device__ float g_ao[(size_t)B_ * S_ * D_];        // attention output [b*s, d]

// ============================================================================
// mma.sync m16n8k16 bf16 (baseline PTX; compiles for plain sm_103)
// bf16 2-split 3-product emulation: D += Ahi*Bhi + Ahi*Blo + Alo*Bhi.
// ============================================================================
#define MMA16816(d, a, b0, b1)                                               \
    asm volatile("mma.sync.aligned.m16n8k16.row.col.f32.bf16.bf16.f32 "      \
                 "{%0,%1,%2,%3}, {%4,%5,%6,%7}, {%8,%9}, {%0,%1,%2,%3};"     \
                 : "+f"((d)[0]), "+f"((d)[1]), "+f"((d)[2]), "+f"((d)[3])    \
                 : "r"((a)[0]), "r"((a)[1]), "r"((a)[2]), "r"((a)[3]),       \
                   "r"(b0), "r"(b1))

__device__ __forceinline__ void split2(float x0, float x1,
                                       uint32_t& hi, uint32_t& lo) {
    __nv_bfloat16 h0 = __float2bfloat16_rn(x0);
    __nv_bfloat16 h1 = __float2bfloat16_rn(x1);
    float r0 = x0 - __bfloat162float(h0);
    float r1 = x1 - __bfloat162float(h1);
    __nv_bfloat16 l0 = __float2bfloat16_rn(r0);
    __nv_bfloat16 l1 = __float2bfloat16_rn(r1);
    hi = (uint32_t)__bfloat16_as_ushort(h0) |
         ((uint32_t)__bfloat16_as_ushort(h1) << 16);
    lo = (uint32_t)__bfloat16_as_ushort(l0) |
         ((uint32_t)__bfloat16_as_ushort(l1) << 16);
}

// ============================================================================
// Double-buffered emulated-bf16 MMA GEMM, dependency-spread MMA scheduling.
// Out[M=8192, N] = A[M,1024] @ W[1024,N] + bias, CTA 128x128, BK=32.
// MODE 0: N=1024, A=g_ao, row-major Out. MODE 1: N=3072, scatter q/k/v.
// ============================================================================
#define KPSTR 18
#define GTILE (128 * KPSTR)
#define GBUF  (4 * GTILE)
#define GEMM_SMEM_BYTES (2 * GBUF * 4)

template <int MODE, int NDIM>
__global__ void __launch_bounds__(256) gemm_mma(
    const float* __restrict__ Ain,
    const float* __restrict__ W,
    const float* __restrict__ bias,
    float* __restrict__ Out)
{
    extern __shared__ uint32_t dsm[];

    const float* A = (MODE == 0) ? g_ao : Ain;

    const int tid = threadIdx.x;
    const int wid = tid >> 5;
    const int lane = tid & 31;
    const int g = lane >> 2;
    const int t = lane & 3;
    const int wm = wid & 3;
    const int wn = wid >> 2;
    const int bm = blockIdx.y * 128;
    const int bn = blockIdx.x * 128;

    const int arow = tid >> 4,  akp = tid & 15;
    const int bn_l = tid & 127, bkp = tid >> 7;

    float acc[2][8][4];
#pragma unroll
    for (int i = 0; i < 2; i++)
#pragma unroll
        for (int j = 0; j < 8; j++)
#pragma unroll
            for (int c = 0; c < 4; c++) acc[i][j][c] = 0.0f;

    // ---- prologue: stage tile 0 into buffer 0 ----
    {
        uint32_t* pAh = dsm;
        uint32_t* pAl = pAh + GTILE;
        uint32_t* pBh = pAl + GTILE;
        uint32_t* pBl = pBh + GTILE;
#pragma unroll
        for (int i = 0; i < 8; i++) {
            int row = arow + i * 16;
            float2 v = *(const float2*)&A[(size_t)(bm + row) * 1024 + akp * 2];
            split2(v.x, v.y, pAh[row * KPSTR + akp], pAl[row * KPSTR + akp]);
        }
#pragma unroll
        for (int i = 0; i < 8; i++) {
            int kp = bkp + i * 2;
            float w0 = W[(size_t)(kp * 2) * NDIM + bn + bn_l];
            float w1 = W[(size_t)(kp * 2 + 1) * NDIM + bn + bn_l];
            split2(w0, w1, pBh[bn_l * KPSTR + kp], pBl[bn_l * KPSTR + kp]);
        }
    }
    __syncthreads();

    float2 ra[8];
    float rb0[8], rb1[8];

    for (int kc = 0; kc < 32; kc++) {
        const int cur = kc & 1;
        const int nxt = cur ^ 1;
        const bool more = (kc + 1 < 32);

        // ---- issue next tile's global loads ----
        if (more) {
            const int k1 = (kc + 1) * 32;
#pragma unroll
            for (int i = 0; i < 8; i++) {
                int row = arow + i * 16;
                ra[i] = *(const float2*)&A[(size_t)(bm + row) * 1024 + k1 + akp * 2];
            }
#pragma unroll
            for (int i = 0; i < 8; i++) {
                int kp = bkp + i * 2;
                rb0[i] = W[(size_t)(k1 + kp * 2) * NDIM + bn + bn_l];
                rb1[i] = W[(size_t)(k1 + kp * 2 + 1) * NDIM + bn + bn_l];
            }
        }

        // ---- MMAs on current buffer, 3-pass dependency-spread order ----
        {
            const uint32_t* pAh = dsm + cur * GBUF;
            const uint32_t* pAl = pAh + GTILE;
            const uint32_t* pBh = pAl + GTILE;
            const uint32_t* pBl = pBh + GTILE;
#pragma unroll
            for (int ks = 0; ks < 2; ks++) {
                const int kp0 = ks * 8;
                uint32_t ah[2][4], al[2][4];
#pragma unroll
                for (int mt = 0; mt < 2; mt++) {
                    int r0 = (wm * 32 + mt * 16 + g) * KPSTR;
                    ah[mt][0] = pAh[r0 + kp0 + t];
                    ah[mt][1] = pAh[r0 + 8 * KPSTR + kp0 + t];
                    ah[mt][2] = pAh[r0 + kp0 + t + 4];
                    ah[mt][3] = pAh[r0 + 8 * KPSTR + kp0 + t + 4];
                    al[mt][0] = pAl[r0 + kp0 + t];
                    al[mt][1] = pAl[r0 + 8 * KPSTR + kp0 + t];
                    al[mt][2] = pAl[r0 + kp0 + t + 4];
                    al[mt][3] = pAl[r0 + 8 * KPSTR + kp0 + t + 4];
                }
                uint32_t bh[8][2], bl[8][2];
#pragma unroll
                for (int nt = 0; nt < 8; nt++) {
                    int nr = (wn * 64 + nt * 8 + g) * KPSTR;
                    bh[nt][0] = pBh[nr + kp0 + t];
                    bh[nt][1] = pBh[nr + kp0 + t + 4];
                    bl[nt][0] = pBl[nr + kp0 + t];
                    bl[nt][1] = pBl[nr + kp0 + t + 4];
                }
                // pass 1: hi*hi (16 independent MMAs)
#pragma unroll
                for (int mt = 0; mt < 2; mt++)
#pragma unroll
                    for (int nt = 0; nt < 8; nt++)
                        MMA16816(acc[mt][nt], ah[mt], bh[nt][0], bh[nt][1]);
                // pass 2: hi*lo
#pragma unroll
                for (int mt = 0; mt < 2; mt++)
#pragma unroll
                    for (int nt = 0; nt < 8; nt++)
                        MMA16816(acc[mt][nt], ah[mt], bl[nt][0], bl[nt][1]);
                // pass 3: lo*hi
#pragma unroll
                for (int mt = 0; mt < 2; mt++)
#pragma unroll
                    for (int nt = 0; nt < 8; nt++)
                        MMA16816(acc[mt][nt], al[mt], bh[nt][0], bh[nt][1]);
            }
        }

        // ---- convert + store next tile ----
        if (more) {
            uint32_t* pAh = dsm + nxt * GBUF;
            uint32_t* pAl = pAh + GTILE;
            uint32_t* pBh = pAl + GTILE;
            uint32_t* pBl = pBh + GTILE;
#pragma unroll
            for (int i = 0; i < 8; i++) {
                int row = arow + i * 16;
                split2(ra[i].x, ra[i].y,
                       pAh[row * KPSTR + akp], pAl[row * KPSTR + akp]);
            }
#pragma unroll
            for (int i = 0; i < 8; i++) {
                int kp = bkp + i * 2;
                split2(rb0[i], rb1[i],
                       pBh[bn_l * KPSTR + kp], pBl[bn_l * KPSTR + kp]);
            }
        }
        __syncthreads();
    }

    // ---- epilogue ----
#pragma unroll
    for (int mt = 0; mt < 2; mt++) {
        int row0 = bm + wm * 32 + mt * 16 + g;
#pragma unroll
        for (int nt = 0; nt < 8; nt++) {
            int col = bn + wn * 64 + nt * 8 + t * 2;
            float b0 = bias[col], b1 = bias[col + 1];
            float2 v0 = make_float2(acc[mt][nt][0] + b0, acc[mt][nt][1] + b1);
            float2 v1 = make_float2(acc[mt][nt][2] + b0, acc[mt][nt][3] + b1);
            if (MODE == 0) {
                *(float2*)&Out[(size_t)row0 * NDIM + col] = v0;
                *(float2*)&Out[(size_t)(row0 + 8) * NDIM + col] = v1;
            } else {
                int which = col >> 10;
                int h = (col & 1023) >> 6;
                int hd = col & 63;
                float* dst = (which == 0) ? g_q : (which == 1) ? g_k : g_v;
                int b = row0 >> 11, s = row0 & 2047;
                *(float2*)&dst[(((size_t)b * H_ + h) * S_ + s) * HD_ + hd] = v0;
                int r1 = row0 + 8;
                b = r1 >> 11; s = r1 & 2047;
                *(float2*)&dst[(((size_t)b * H_ + h) * S_ + s) * HD_ + hd] = v1;
            }
        }
    }
}

// ============================================================================
// Flash attention on emulated-bf16 HMMA, double-buffered K/V,
// dependency-spread MMA scheduling in QK^T and PV.
// ============================================================================
#define KPV 36
#define QTILE (128 * KPV)
#define KVTILE (64 * KPV)
#define KVBUF (4 * KVTILE)
#define FLASH_SMEM_BYTES ((2 * QTILE + 2 * KVBUF) * 4)

__global__ void __launch_bounds__(256) flash_mma()
{
    extern __shared__ uint32_t su[];
    uint32_t* sQh = su;
    uint32_t* sQl = sQh + QTILE;
    uint32_t* kvbase = sQl + QTILE;

    const int z  = blockIdx.x;
    const int bh = z >> 4;
    const int qt = 15 - (z & 15);
    const int b  = bh >> 4;
    const int h  = bh & 15;

    const int tid = threadIdx.x;
    const int wid = tid >> 5;
    const int lane = tid & 31;
    const int g = lane >> 2;
    const int t = lane & 3;

    const float NEG_INF = __int_as_float(0xff800000);

    const float* kbase = g_k + (size_t)bh * S_ * HD_;
    const float* vbase = g_v + (size_t)bh * S_ * HD_;

    // ---- stage Q (pre-scaled), single buffer ----
    {
        const float* qb = g_q + ((size_t)bh * S_ + qt * 128) * HD_;
#pragma unroll
        for (int i = 0; i < 16; i++) {
            int idx = tid + i * 256;
            int row = idx >> 5, kp = idx & 31;
            float2 v = *(const float2*)&qb[row * 64 + kp * 2];
            split2(v.x * 0.125f, v.y * 0.125f,
                   sQh[row * KPV + kp], sQl[row * KPV + kp]);
        }
    }

    float m0 = NEG_INF, m1 = NEG_INF, l0 = 0.0f, l1 = 0.0f;
    float acco[8][4];
#pragma unroll
    for (int nt = 0; nt < 8; nt++)
#pragma unroll
        for (int c = 0; c < 4; c++) acco[nt][c] = 0.0f;

    const int ktmax = 2 * qt + 1;
    const int rg0 = qt * 128 + wid * 16 + g;
    const int warp_row_hi = qt * 128 + wid * 16 + 15;

    // ---- prologue: stage K/V tile 0 into buffer 0 ----
    {
        uint32_t* pKh = kvbase;
        uint32_t* pKl = pKh + KVTILE;
        uint32_t* pVh = pKl + KVTILE;
        uint32_t* pVl = pVh + KVTILE;
#pragma unroll
        for (int i = 0; i < 8; i++) {
            int idx = tid + i * 256;
            int row = idx >> 5, kp = idx & 31;
            float2 v = *(const float2*)&kbase[(size_t)row * 64 + kp * 2];
            split2(v.x, v.y, pKh[row * KPV + kp], pKl[row * KPV + kp]);
        }
#pragma unroll
        for (int i = 0; i < 8; i++) {
            int idx = tid + i * 256;
            int hd = idx & 63, sp = idx >> 6;
            float v0 = vbase[(size_t)(sp * 2) * 64 + hd];
            float v1 = vbase[(size_t)(sp * 2 + 1) * 64 + hd];
            split2(v0, v1, pVh[hd * KPV + sp], pVl[hd * KPV + sp]);
        }
    }
    __syncthreads();

    float2 rk[8];
    float rv0[8], rv1[8];

    for (int kt = 0; kt <= ktmax; kt++) {
        const int cur = kt & 1;
        const int nxt = cur ^ 1;
        const bool more = (kt < ktmax);

        // ---- issue next K/V tile's global loads ----
        if (more) {
            const float* kbp = kbase + (size_t)(kt + 1) * 64 * HD_;
            const float* vbp = vbase + (size_t)(kt + 1) * 64 * HD_;
#pragma unroll
            for (int i = 0; i < 8; i++) {
                int idx = tid + i * 256;
                int row = idx >> 5, kp = idx & 31;
                rk[i] = *(const float2*)&kbp[(size_t)row * 64 + kp * 2];
            }
#pragma unroll
            for (int i = 0; i < 8; i++) {
                int idx = tid + i * 256;
                int hd = idx & 63, sp = idx >> 6;
                rv0[i] = vbp[(size_t)(sp * 2) * 64 + hd];
                rv1[i] = vbp[(size_t)(sp * 2 + 1) * 64 + hd];
            }
        }

        // ---- compute on current buffer ----
        if (warp_row_hi >= kt * 64) {
            const uint32_t* pKh = kvbase + cur * KVBUF;
            const uint32_t* pKl = pKh + KVTILE;
            const uint32_t* pVh = pKl + KVTILE;
            const uint32_t* pVl = pVh + KVTILE;

            // QK^T (3-pass spread per ks)
            float accs[8][4];
#pragma unroll
            for (int nt = 0; nt < 8; nt++)
#pragma unroll
                for (int c = 0; c < 4; c++) accs[nt][c] = 0.0f;

#pragma unroll
            for (int ks = 0; ks < 4; ks++) {
                const int r0s = (wid * 16 + g) * KPV;
                const int kpb = ks * 8 + t;
                uint32_t ah[4] = { sQh[r0s + kpb],     sQh[r0s + 8 * KPV + kpb],
                                   sQh[r0s + kpb + 4], sQh[r0s + 8 * KPV + kpb + 4] };
                uint32_t al[4] = { sQl[r0s + kpb],     sQl[r0s + 8 * KPV + kpb],
                                   sQl[r0s + kpb + 4], sQl[r0s + 8 * KPV + kpb + 4] };
                uint32_t bh[8][2], bl[8][2];
#pragma unroll
                for (int nt = 0; nt < 8; nt++) {
                    int nr = (nt * 8 + g) * KPV;
                    bh[nt][0] = pKh[nr + kpb];
                    bh[nt][1] = pKh[nr + kpb + 4];
                    bl[nt][0] = pKl[nr + kpb];
                    bl[nt][1] = pKl[nr + kpb + 4];
                }
#pragma unroll
                for (int nt = 0; nt < 8; nt++)
                    MMA16816(accs[nt], ah, bh[nt][0], bh[nt][1]);
#pragma unroll
                for (int nt = 0; nt < 8; nt++)
                    MMA16816(accs[nt], ah, bl[nt][0], bl[nt][1]);
#pragma unroll
                for (int nt = 0; nt < 8; nt++)
                    MMA16816(accs[nt], al, bh[nt][0], bh[nt][1]);
            }

            // causal mask
            if (kt >= 2 * qt) {
                const int rg1 = rg0 + 8;
#pragma unroll
                for (int nt = 0; nt < 8; nt++) {
                    int c0 = kt * 64 + nt * 8 + t * 2;
                    int c1 = c0 + 1;
                    if (c0 > rg0) accs[nt][0] = NEG_INF;
                    if (c1 > rg0) accs[nt][1] = NEG_INF;
                    if (c0 > rg1) accs[nt][2] = NEG_INF;
                    if (c1 > rg1) accs[nt][3] = NEG_INF;
                }
            }

            // warp-local online softmax
            float rm0 = NEG_INF, rm1 = NEG_INF;
#pragma unroll
            for (int nt = 0; nt < 8; nt++) {
                rm0 = fmaxf(rm0, fmaxf(accs[nt][0], accs[nt][1]));
                rm1 = fmaxf(rm1, fmaxf(accs[nt][2], accs[nt][3]));
            }
            rm0 = fmaxf(rm0, __shfl_xor_sync(0xFFFFFFFF, rm0, 1));
            rm0 = fmaxf(rm0, __shfl_xor_sync(0xFFFFFFFF, rm0, 2));
            rm1 = fmaxf(rm1, __shfl_xor_sync(0xFFFFFFFF, rm1, 1));
            rm1 = fmaxf(rm1, __shfl_xor_sync(0xFFFFFFFF, rm1, 2));

            float mn0 = fmaxf(m0, rm0), mn1 = fmaxf(m1, rm1);
            float a0 = __expf(m0 - mn0);
            float a1 = __expf(m1 - mn1);

            uint32_t pah[4][4], pal[4][4];
            float rs0 = 0.0f, rs1 = 0.0f;
#pragma unroll
            for (int nt = 0; nt < 8; nt++) {
                float p0 = __expf(accs[nt][0] - mn0);
                float p1 = __expf(accs[nt][1] - mn0);
                float p2 = __expf(accs[nt][2] - mn1);
                float p3 = __expf(accs[nt][3] - mn1);
                rs0 += p0 + p1;
                rs1 += p2 + p3;
                uint32_t h01, l01, h23, l23;
                split2(p0, p1, h01, l01);
                split2(p2, p3, h23, l23);
                int ks = nt >> 1, half = nt & 1;
                pah[ks][half * 2]     = h01;
                pah[ks][half * 2 + 1] = h23;
                pal[ks][half * 2]     = l01;
                pal[ks][half * 2 + 1] = l23;
            }
            rs0 += __shfl_xor_sync(0xFFFFFFFF, rs0, 1);
            rs0 += __shfl_xor_sync(0xFFFFFFFF, rs0, 2);
            rs1 += __shfl_xor_sync(0xFFFFFFFF, rs1, 1);
            rs1 += __shfl_xor_sync(0xFFFFFFFF, rs1, 2);

            l0 = l0 * a0 + rs0;
            l1 = l1 * a1 + rs1;
            m0 = mn0;
            m1 = mn1;

#pragma unroll
            for (int nt = 0; nt < 8; nt++) {
                acco[nt][0] *= a0; acco[nt][1] *= a0;
                acco[nt][2] *= a1; acco[nt][3] *= a1;
            }

            // PV (3-pass spread per ks)
#pragma unroll
            for (int ks = 0; ks < 4; ks++) {
                const int kpb = ks * 8 + t;
                uint32_t vh[8][2], vl[8][2];
#pragma unroll
                for (int nt = 0; nt < 8; nt++) {
                    int nr = (nt * 8 + g) * KPV;
                    vh[nt][0] = pVh[nr + kpb];
                    vh[nt][1] = pVh[nr + kpb + 4];
                    vl[nt][0] = pVl[nr + kpb];
                    vl[nt][1] = pVl[nr + kpb + 4];
                }
#pragma unroll
                for (int nt = 0; nt < 8; nt++)
                    MMA16816(acco[nt], pah[ks], vh[nt][0], vh[nt][1]);
#pragma unroll
                for (int nt = 0; nt < 8; nt++)
                    MMA16816(acco[nt], pal[ks], vh[nt][0], vh[nt][1]);
#pragma unroll
                for (int nt = 0; nt < 8; nt++)
                    MMA16816(acco[nt], pah[ks], vl[nt][0], vl[nt][1]);
            }
        }

        // ---- convert + store next K/V tile ----
        if (more) {
            uint32_t* pKh = kvbase + nxt * KVBUF;
            uint32_t* pKl = pKh + KVTILE;
            uint32_t* pVh = pKl + KVTILE;
            uint32_t* pVl = pVh + KVTILE;
#pragma unroll
            for (int i = 0; i < 8; i++) {
                int idx = tid + i * 256;
                int row = idx >> 5, kp = idx & 31;
                split2(rk[i].x, rk[i].y,
                       pKh[row * KPV + kp], pKl[row * KPV + kp]);
            }
#pragma unroll
            for (int i = 0; i < 8; i++) {
                int idx = tid + i * 256;
                int hd = idx & 63, sp = idx >> 6;
                split2(rv0[i], rv1[i],
                       pVh[hd * KPV + sp], pVl[hd * KPV + sp]);
            }
        }
        __syncthreads();
    }

    // ---- epilogue: O / l -> g_ao[b*s][h*64 + c] ----
    const float i0 = 1.0f / l0;
    const float i1 = 1.0f / l1;
    const int sq = qt * 128 + wid * 16 + g;
#pragma unroll
    for (int nt = 0; nt < 8; nt++) {
        int col = h * 64 + nt * 8 + t * 2;
        float2 v0 = make_float2(acco[nt][0] * i0, acco[nt][1] * i0);
        float2 v1 = make_float2(acco[nt][2] * i1, acco[nt][3] * i1);
        *(float2*)&g_ao[((size_t)b * S_ + sq) * D_ + col] = v0;
        *(float2*)&g_ao[((size_t)b * S_ + sq + 8) * D_ + col] = v1;
    }
}

// ============================================================================
// Launch
// ============================================================================
extern "C" void kernel_launch(void* const* d_in, const int* in_sizes, int n_in,
                              void* d_out, int out_size)
{
    const float *x = nullptr, *w_attn = nullptr, *b_attn = nullptr;
    const float *w_proj = nullptr, *b_proj = nullptr;
    for (int i = 0; i < n_in; i++) {
        switch (in_sizes[i]) {
            case 8388608: x      = (const float*)d_in[i]; break;
            case 3145728: w_attn = (const float*)d_in[i]; break;
            case 3072:    b_attn = (const float*)d_in[i]; break;
            case 1048576: w_proj = (const float*)d_in[i]; break;
            case 1024:    b_proj = (const float*)d_in[i]; break;
            default: break;  // mask (ignored; causal handled analytically)
        }
    }
    if (!x)      x      = (const float*)d_in[0];
    if (!w_attn) w_attn = (const float*)d_in[2];
    if (!b_attn) b_attn = (const float*)d_in[3];
    if (!w_proj) w_proj = (const float*)d_in[4];
    if (!b_proj) b_proj = (const float*)d_in[5];

    const int M = B_ * S_;  // 8192

    cudaFuncSetAttribute(gemm_mma<1, 3072>,
                         cudaFuncAttributeMaxDynamicSharedMemorySize,
                         GEMM_SMEM_BYTES);
    cudaFuncSetAttribute(gemm_mma<0, 1024>,
                         cudaFuncAttributeMaxDynamicSharedMemorySize,
                         GEMM_SMEM_BYTES);
    cudaFuncSetAttribute(flash_mma,
                         cudaFuncAttributeMaxDynamicSharedMemorySize,
                         FLASH_SMEM_BYTES);

    // 1) QKV projection (pipelined emulated-bf16 MMA), scatter to [b,h,s,hd]
    gemm_mma<1, 3072><<<dim3(3 * D_ / 128, M / 128), 256, GEMM_SMEM_BYTES>>>(
        x, w_attn, b_attn, nullptr);

    // 2) Fused causal flash attention (pipelined emulated-bf16 MMA)
    flash_mma<<<B_ * H_ * (S_ / 128), 256, FLASH_SMEM_BYTES>>>();

    // 3) Output projection (pipelined emulated-bf16 MMA) -> d_out
    gemm_mma<0, 1024><<<dim3(D_ / 128, M / 128), 256, GEMM_SMEM_BYTES>>>(
        nullptr, w_proj, b_proj, (float*)d_out);
}

// round 10
// speedup vs baseline: 2.7793x; 1.1259x over previous
#include <cuda_runtime.h>
#include <cuda_bf16.h>
#include <cstdint>

// Problem constants: B=4, S=2048, D=1024, H=16, HD=64
#define B_ 4
#define H_ 16
#define S_ 2048
#define D_ 1024
#define HD_ 64

// Scratch (allocation-free rule: __device__ globals).
__device__ float g_q[(size_t)B_ * H_ * S_ * HD_];   // [b,h,s,hd]
__device__ float g_k[(size_t)B_ * H_ * S_ * HD_];
__device__ float g_v[(size_t)B_ * H_ * S_ * HD_];
__device__ float g_ao[(size_t)B_ * S_ * D_];        // attention output [b*s, d]

// ============================================================================
// mma.sync m16n8k16 bf16 (baseline PTX; compiles for plain sm_103)
// bf16 2-split 3-product emulation: D += Ahi*Bhi + Ahi*Blo + Alo*Bhi.
// ============================================================================
#define MMA16816(d, a, b0, b1)                                               \
    asm volatile("mma.sync.aligned.m16n8k16.row.col.f32.bf16.bf16.f32 "      \
                 "{%0,%1,%2,%3}, {%4,%5,%6,%7}, {%8,%9}, {%0,%1,%2,%3};"     \
                 : "+f"((d)[0]), "+f"((d)[1]), "+f"((d)[2]), "+f"((d)[3])    \
                 : "r"((a)[0]), "r"((a)[1]), "r"((a)[2]), "r"((a)[3]),       \
                   "r"(b0), "r"(b1))

__device__ __forceinline__ void split2(float x0, float x1,
                                       uint32_t& hi, uint32_t& lo) {
    __nv_bfloat16 h0 = __float2bfloat16_rn(x0);
    __nv_bfloat16 h1 = __float2bfloat16_rn(x1);
    float r0 = x0 - __bfloat162float(h0);
    float r1 = x1 - __bfloat162float(h1);
    __nv_bfloat16 l0 = __float2bfloat16_rn(r0);
    __nv_bfloat16 l1 = __float2bfloat16_rn(r1);
    hi = (uint32_t)__bfloat16_as_ushort(h0) |
         ((uint32_t)__bfloat16_as_ushort(h1) << 16);
    lo = (uint32_t)__bfloat16_as_ushort(l0) |
         ((uint32_t)__bfloat16_as_ushort(l1) << 16);
}

// ============================================================================
// Emulated-bf16 MMA GEMM, 2 CTAs/SM (latency hidden cross-CTA).
// Out[M=8192, N] = A[M,1024] @ W[1024,N] + bias, CTA 128x128, BK=32.
// Single-buffered 36KB static smem; __launch_bounds__(256,2) caps regs.
// MODE 0: N=1024, A=g_ao, row-major Out. MODE 1: N=3072, scatter q/k/v.
// ============================================================================
#define KPSTR 18
#define GTILE (128 * KPSTR)

template <int MODE, int NDIM>
__global__ void __launch_bounds__(256, 2) gemm_mma(
    const float* __restrict__ Ain,
    const float* __restrict__ W,
    const float* __restrict__ bias,
    float* __restrict__ Out)
{
    __shared__ uint32_t sm[4 * GTILE];   // 36 KB

    const float* A = (MODE == 0) ? g_ao : Ain;

    const int tid = threadIdx.x;
    const int wid = tid >> 5;
    const int lane = tid & 31;
    const int g = lane >> 2;
    const int t = lane & 3;
    const int wm = wid & 3;
    const int wn = wid >> 2;
    const int bm = blockIdx.y * 128;
    const int bn = blockIdx.x * 128;

    const int arow = tid >> 4,  akp = tid & 15;
    const int bn_l = tid & 127, bkp = tid >> 7;

    uint32_t* pAh = sm;
    uint32_t* pAl = pAh + GTILE;
    uint32_t* pBh = pAl + GTILE;
    uint32_t* pBl = pBh + GTILE;

    float acc[2][8][4];
#pragma unroll
    for (int i = 0; i < 2; i++)
#pragma unroll
        for (int j = 0; j < 8; j++)
#pragma unroll
            for (int c = 0; c < 4; c++) acc[i][j][c] = 0.0f;

    for (int kc = 0; kc < 32; kc++) {
        const int k0 = kc * 32;
        // ---- stage A (fp32 -> bf16 hi/lo) ----
#pragma unroll
        for (int i = 0; i < 8; i++) {
            int row = arow + i * 16;
            float2 v = *(const float2*)&A[(size_t)(bm + row) * 1024 + k0 + akp * 2];
            split2(v.x, v.y, pAh[row * KPSTR + akp], pAl[row * KPSTR + akp]);
        }
        // ---- stage B (transpose w[k][n] -> smem[n][kpair]) ----
#pragma unroll
        for (int i = 0; i < 8; i++) {
            int kp = bkp + i * 2;
            float w0 = W[(size_t)(k0 + kp * 2) * NDIM + bn + bn_l];
            float w1 = W[(size_t)(k0 + kp * 2 + 1) * NDIM + bn + bn_l];
            split2(w0, w1, pBh[bn_l * KPSTR + kp], pBl[bn_l * KPSTR + kp]);
        }
        __syncthreads();

        // ---- MMAs ----
#pragma unroll
        for (int ks = 0; ks < 2; ks++) {
            const int kp0 = ks * 8;
            uint32_t ah[2][4], al[2][4];
#pragma unroll
            for (int mt = 0; mt < 2; mt++) {
                int r0 = (wm * 32 + mt * 16 + g) * KPSTR;
                ah[mt][0] = pAh[r0 + kp0 + t];
                ah[mt][1] = pAh[r0 + 8 * KPSTR + kp0 + t];
                ah[mt][2] = pAh[r0 + kp0 + t + 4];
                ah[mt][3] = pAh[r0 + 8 * KPSTR + kp0 + t + 4];
                al[mt][0] = pAl[r0 + kp0 + t];
                al[mt][1] = pAl[r0 + 8 * KPSTR + kp0 + t];
                al[mt][2] = pAl[r0 + kp0 + t + 4];
                al[mt][3] = pAl[r0 + 8 * KPSTR + kp0 + t + 4];
            }
#pragma unroll
            for (int nt = 0; nt < 8; nt++) {
                int nr = (wn * 64 + nt * 8 + g) * KPSTR;
                uint32_t bh0 = pBh[nr + kp0 + t];
                uint32_t bh1 = pBh[nr + kp0 + t + 4];
                uint32_t bl0 = pBl[nr + kp0 + t];
                uint32_t bl1 = pBl[nr + kp0 + t + 4];
#pragma unroll
                for (int mt = 0; mt < 2; mt++) {
                    MMA16816(acc[mt][nt], ah[mt], bh0, bh1);
                    MMA16816(acc[mt][nt], ah[mt], bl0, bl1);
                    MMA16816(acc[mt][nt], al[mt], bh0, bh1);
                }
            }
        }
        __syncthreads();
    }

    // ---- epilogue ----
#pragma unroll
    for (int mt = 0; mt < 2; mt++) {
        int row0 = bm + wm * 32 + mt * 16 + g;
#pragma unroll
        for (int nt = 0; nt < 8; nt++) {
            int col = bn + wn * 64 + nt * 8 + t * 2;
            float b0 = bias[col], b1 = bias[col + 1];
            float2 v0 = make_float2(acc[mt][nt][0] + b0, acc[mt][nt][1] + b1);
            float2 v1 = make_float2(acc[mt][nt][2] + b0, acc[mt][nt][3] + b1);
            if (MODE == 0) {
                *(float2*)&Out[(size_t)row0 * NDIM + col] = v0;
                *(float2*)&Out[(size_t)(row0 + 8) * NDIM + col] = v1;
            } else {
                int which = col >> 10;
                int h = (col & 1023) >> 6;
                int hd = col & 63;
                float* dst = (which == 0) ? g_q : (which == 1) ? g_k : g_v;
                int b = row0 >> 11, s = row0 & 2047;
                *(float2*)&dst[(((size_t)b * H_ + h) * S_ + s) * HD_ + hd] = v0;
                int r1 = row0 + 8;
                b = r1 >> 11; s = r1 & 2047;
                *(float2*)&dst[(((size_t)b * H_ + h) * S_ + s) * HD_ + hd] = v1;
            }
        }
    }
}

// ============================================================================
// Flash attention on emulated-bf16 HMMA, double-buffered K/V (unchanged R9).
// ============================================================================
#define KPV 36
#define QTILE (128 * KPV)
#define KVTILE (64 * KPV)
#define KVBUF (4 * KVTILE)
#define FLASH_SMEM_BYTES ((2 * QTILE + 2 * KVBUF) * 4)

__global__ void __launch_bounds__(256) flash_mma()
{
    extern __shared__ uint32_t su[];
    uint32_t* sQh = su;
    uint32_t* sQl = sQh + QTILE;
    uint32_t* kvbase = sQl + QTILE;

    const int z  = blockIdx.x;
    const int bh = z >> 4;
    const int qt = 15 - (z & 15);
    const int b  = bh >> 4;
    const int h  = bh & 15;

    const int tid = threadIdx.x;
    const int wid = tid >> 5;
    const int lane = tid & 31;
    const int g = lane >> 2;
    const int t = lane & 3;

    const float NEG_INF = __int_as_float(0xff800000);

    const float* kbase = g_k + (size_t)bh * S_ * HD_;
    const float* vbase = g_v + (size_t)bh * S_ * HD_;

    // ---- stage Q (pre-scaled), single buffer ----
    {
        const float* qb = g_q + ((size_t)bh * S_ + qt * 128) * HD_;
#pragma unroll
        for (int i = 0; i < 16; i++) {
            int idx = tid + i * 256;
            int row = idx >> 5, kp = idx & 31;
            float2 v = *(const float2*)&qb[row * 64 + kp * 2];
            split2(v.x * 0.125f, v.y * 0.125f,
                   sQh[row * KPV + kp], sQl[row * KPV + kp]);
        }
    }

    float m0 = NEG_INF, m1 = NEG_INF, l0 = 0.0f, l1 = 0.0f;
    float acco[8][4];
#pragma unroll
    for (int nt = 0; nt < 8; nt++)
#pragma unroll
        for (int c = 0; c < 4; c++) acco[nt][c] = 0.0f;

    const int ktmax = 2 * qt + 1;
    const int rg0 = qt * 128 + wid * 16 + g;
    const int warp_row_hi = qt * 128 + wid * 16 + 15;

    // ---- prologue: stage K/V tile 0 into buffer 0 ----
    {
        uint32_t* pKh = kvbase;
        uint32_t* pKl = pKh + KVTILE;
        uint32_t* pVh = pKl + KVTILE;
        uint32_t* pVl = pVh + KVTILE;
#pragma unroll
        for (int i = 0; i < 8; i++) {
            int idx = tid + i * 256;
            int row = idx >> 5, kp = idx & 31;
            float2 v = *(const float2*)&kbase[(size_t)row * 64 + kp * 2];
            split2(v.x, v.y, pKh[row * KPV + kp], pKl[row * KPV + kp]);
        }
#pragma unroll
        for (int i = 0; i < 8; i++) {
            int idx = tid + i * 256;
            int hd = idx & 63, sp = idx >> 6;
            float v0 = vbase[(size_t)(sp * 2) * 64 + hd];
            float v1 = vbase[(size_t)(sp * 2 + 1) * 64 + hd];
            split2(v0, v1, pVh[hd * KPV + sp], pVl[hd * KPV + sp]);
        }
    }
    __syncthreads();

    float2 rk[8];
    float rv0[8], rv1[8];

    for (int kt = 0; kt <= ktmax; kt++) {
        const int cur = kt & 1;
        const int nxt = cur ^ 1;
        const bool more = (kt < ktmax);

        // ---- issue next K/V tile's global loads ----
        if (more) {
            const float* kbp = kbase + (size_t)(kt + 1) * 64 * HD_;
            const float* vbp = vbase + (size_t)(kt + 1) * 64 * HD_;
#pragma unroll
            for (int i = 0; i < 8; i++) {
                int idx = tid + i * 256;
                int row = idx >> 5, kp = idx & 31;
                rk[i] = *(const float2*)&kbp[(size_t)row * 64 + kp * 2];
            }
#pragma unroll
            for (int i = 0; i < 8; i++) {
                int idx = tid + i * 256;
                int hd = idx & 63, sp = idx >> 6;
                rv0[i] = vbp[(size_t)(sp * 2) * 64 + hd];
                rv1[i] = vbp[(size_t)(sp * 2 + 1) * 64 + hd];
            }
        }

        // ---- compute on current buffer ----
        if (warp_row_hi >= kt * 64) {
            const uint32_t* pKh = kvbase + cur * KVBUF;
            const uint32_t* pKl = pKh + KVTILE;
            const uint32_t* pVh = pKl + KVTILE;
            const uint32_t* pVl = pVh + KVTILE;

            // QK^T
            float accs[8][4];
#pragma unroll
            for (int nt = 0; nt < 8; nt++)
#pragma unroll
                for (int c = 0; c < 4; c++) accs[nt][c] = 0.0f;

#pragma unroll
            for (int ks = 0; ks < 4; ks++) {
                const int r0s = (wid * 16 + g) * KPV;
                const int kpb = ks * 8 + t;
                uint32_t ah[4] = { sQh[r0s + kpb],     sQh[r0s + 8 * KPV + kpb],
                                   sQh[r0s + kpb + 4], sQh[r0s + 8 * KPV + kpb + 4] };
                uint32_t al[4] = { sQl[r0s + kpb],     sQl[r0s + 8 * KPV + kpb],
                                   sQl[r0s + kpb + 4], sQl[r0s + 8 * KPV + kpb + 4] };
#pragma unroll
                for (int nt = 0; nt < 8; nt++) {
                    int nr = (nt * 8 + g) * KPV;
                    uint32_t bh0 = pKh[nr + kpb], bh1 = pKh[nr + kpb + 4];
                    uint32_t bl0 = pKl[nr + kpb], bl1 = pKl[nr + kpb + 4];
                    MMA16816(accs[nt], ah, bh0, bh1);
                    MMA16816(accs[nt], ah, bl0, bl1);
                    MMA16816(accs[nt], al, bh0, bh1);
                }
            }

            // causal mask
            if (kt >= 2 * qt) {
                const int rg1 = rg0 + 8;
#pragma unroll
                for (int nt = 0; nt < 8; nt++) {
                    int c0 = kt * 64 + nt * 8 + t * 2;
                    int c1 = c0 + 1;
                    if (c0 > rg0) accs[nt][0] = NEG_INF;
                    if (c1 > rg0) accs[nt][1] = NEG_INF;
                    if (c0 > rg1) accs[nt][2] = NEG_INF;
                    if (c1 > rg1) accs[nt][3] = NEG_INF;
                }
            }

            // warp-local online softmax
            float rm0 = NEG_INF, rm1 = NEG_INF;
#pragma unroll
            for (int nt = 0; nt < 8; nt++) {
                rm0 = fmaxf(rm0, fmaxf(accs[nt][0], accs[nt][1]));
                rm1 = fmaxf(rm1, fmaxf(accs[nt][2], accs[nt][3]));
            }
            rm0 = fmaxf(rm0, __shfl_xor_sync(0xFFFFFFFF, rm0, 1));
            rm0 = fmaxf(rm0, __shfl_xor_sync(0xFFFFFFFF, rm0, 2));
            rm1 = fmaxf(rm1, __shfl_xor_sync(0xFFFFFFFF, rm1, 1));
            rm1 = fmaxf(rm1, __shfl_xor_sync(0xFFFFFFFF, rm1, 2));

            float mn0 = fmaxf(m0, rm0), mn1 = fmaxf(m1, rm1);
            float a0 = __expf(m0 - mn0);
            float a1 = __expf(m1 - mn1);

            uint32_t pah[4][4], pal[4][4];
            float rs0 = 0.0f, rs1 = 0.0f;
#pragma unroll
            for (int nt = 0; nt < 8; nt++) {
                float p0 = __expf(accs[nt][0] - mn0);
                float p1 = __expf(accs[nt][1] - mn0);
                float p2 = __expf(accs[nt][2] - mn1);
                float p3 = __expf(accs[nt][3] - mn1);
                rs0 += p0 + p1;
                rs1 += p2 + p3;
                uint32_t h01, l01, h23, l23;
                split2(p0, p1, h01, l01);
                split2(p2, p3, h23, l23);
                int ks = nt >> 1, half = nt & 1;
                pah[ks][half * 2]     = h01;
                pah[ks][half * 2 + 1] = h23;
                pal[ks][half * 2]     = l01;
                pal[ks][half * 2 + 1] = l23;
            }
            rs0 += __shfl_xor_sync(0xFFFFFFFF, rs0, 1);
            rs0 += __shfl_xor_sync(0xFFFFFFFF, rs0, 2);
            rs1 += __shfl_xor_sync(0xFFFFFFFF, rs1, 1);
            rs1 += __shfl_xor_sync(0xFFFFFFFF, rs1, 2);

            l0 = l0 * a0 + rs0;
            l1 = l1 * a1 + rs1;
            m0 = mn0;
            m1 = mn1;

#pragma unroll
            for (int nt = 0; nt < 8; nt++) {
                acco[nt][0] *= a0; acco[nt][1] *= a0;
                acco[nt][2] *= a1; acco[nt][3] *= a1;
            }

            // PV
#pragma unroll
            for (int ks = 0; ks < 4; ks++) {
                const int kpb = ks * 8 + t;
#pragma unroll
                for (int nt = 0; nt < 8; nt++) {
                    int nr = (nt * 8 + g) * KPV;
                    uint32_t bh0 = pVh[nr + kpb], bh1 = pVh[nr + kpb + 4];
                    uint32_t bl0 = pVl[nr + kpb], bl1 = pVl[nr + kpb + 4];
                    MMA16816(acco[nt], pah[ks], bh0, bh1);
                    MMA16816(acco[nt], pal[ks], bh0, bh1);
                    MMA16816(acco[nt], pah[ks], bl0, bl1);
                }
            }
        }

        // ---- convert + store next K/V tile ----
        if (more) {
            uint32_t* pKh = kvbase + nxt * KVBUF;
            uint32_t* pKl = pKh + KVTILE;
            uint32_t* pVh = pKl + KVTILE;
            uint32_t* pVl = pVh + KVTILE;
#pragma unroll
            for (int i = 0; i < 8; i++) {
                int idx = tid + i * 256;
                int row = idx >> 5, kp = idx & 31;
                split2(rk[i].x, rk[i].y,
                       pKh[row * KPV + kp], pKl[row * KPV + kp]);
            }
#pragma unroll
            for (int i = 0; i < 8; i++) {
                int idx = tid + i * 256;
                int hd = idx & 63, sp = idx >> 6;
                split2(rv0[i], rv1[i],
                       pVh[hd * KPV + sp], pVl[hd * KPV + sp]);
            }
        }
        __syncthreads();
    }

    // ---- epilogue: O / l -> g_ao[b*s][h*64 + c] ----
    const float i0 = 1.0f / l0;
    const float i1 = 1.0f / l1;
    const int sq = qt * 128 + wid * 16 + g;
#pragma unroll
    for (int nt = 0; nt < 8; nt++) {
        int col = h * 64 + nt * 8 + t * 2;
        float2 v0 = make_float2(acco[nt][0] * i0, acco[nt][1] * i0);
        float2 v1 = make_float2(acco[nt][2] * i1, acco[nt][3] * i1);
        *(float2*)&g_ao[((size_t)b * S_ + sq) * D_ + col] = v0;
        *(float2*)&g_ao[((size_t)b * S_ + sq + 8) * D_ + col] = v1;
    }
}

// ============================================================================
// Launch
// ============================================================================
extern "C" void kernel_launch(void* const* d_in, const int* in_sizes, int n_in,
                              void* d_out, int out_size)
{
    const float *x = nullptr, *w_attn = nullptr, *b_attn = nullptr;
    const float *w_proj = nullptr, *b_proj = nullptr;
    for (int i = 0; i < n_in; i++) {
        switch (in_sizes[i]) {
            case 8388608: x      = (const float*)d_in[i]; break;
            case 3145728: w_attn = (const float*)d_in[i]; break;
            case 3072:    b_attn = (const float*)d_in[i]; break;
            case 1048576: w_proj = (const float*)d_in[i]; break;
            case 1024:    b_proj = (const float*)d_in[i]; break;
            default: break;  // mask (ignored; causal handled analytically)
        }
    }
    if (!x)      x      = (const float*)d_in[0];
    if (!w_attn) w_attn = (const float*)d_in[2];
    if (!b_attn) b_attn = (const float*)d_in[3];
    if (!w_proj) w_proj = (const float*)d_in[4];
    if (!b_proj) b_proj = (const float*)d_in[5];

    const int M = B_ * S_;  // 8192

    cudaFuncSetAttribute(flash_mma,
                         cudaFuncAttributeMaxDynamicSharedMemorySize,
                         FLASH_SMEM_BYTES);

    // 1) QKV projection (2 CTAs/SM emulated-bf16 MMA), scatter to [b,h,s,hd]
    gemm_mma<1, 3072><<<dim3(3 * D_ / 128, M / 128), 256>>>(
        x, w_attn, b_attn, nullptr);

    // 2) Fused causal flash attention (pipelined emulated-bf16 MMA)
    flash_mma<<<B_ * H_ * (S_ / 128), 256, FLASH_SMEM_BYTES>>>();

    // 3) Output projection (2 CTAs/SM emulated-bf16 MMA) -> d_out
    gemm_mma<0, 1024><<<dim3(D_ / 128, M / 128), 256>>>(
        nullptr, w_proj, b_proj, (float*)d_out);
}

// round 11
// speedup vs baseline: 3.0597x; 1.1009x over previous
#include <cuda_runtime.h>
#include <cuda_bf16.h>
#include <cstdint>

// Problem constants: B=4, S=2048, D=1024, H=16, HD=64
#define B_ 4
#define H_ 16
#define S_ 2048
#define D_ 1024
#define HD_ 64

// Scratch (allocation-free rule: __device__ globals).
__device__ float g_q[(size_t)B_ * H_ * S_ * HD_];   // [b,h,s,hd]
__device__ float g_k[(size_t)B_ * H_ * S_ * HD_];
__device__ float g_v[(size_t)B_ * H_ * S_ * HD_];
__device__ float g_ao[(size_t)B_ * S_ * D_];        // attention output [b*s, d]

// ============================================================================
// mma.sync m16n8k16 bf16 (baseline PTX; compiles for plain sm_103)
// bf16 2-split 3-product emulation: D += Ahi*Bhi + Ahi*Blo + Alo*Bhi.
// ============================================================================
#define MMA16816(d, a, b0, b1)                                               \
    asm volatile("mma.sync.aligned.m16n8k16.row.col.f32.bf16.bf16.f32 "      \
                 "{%0,%1,%2,%3}, {%4,%5,%6,%7}, {%8,%9}, {%0,%1,%2,%3};"     \
                 : "+f"((d)[0]), "+f"((d)[1]), "+f"((d)[2]), "+f"((d)[3])    \
                 : "r"((a)[0]), "r"((a)[1]), "r"((a)[2]), "r"((a)[3]),       \
                   "r"(b0), "r"(b1))

__device__ __forceinline__ void split2(float x0, float x1,
                                       uint32_t& hi, uint32_t& lo) {
    __nv_bfloat16 h0 = __float2bfloat16_rn(x0);
    __nv_bfloat16 h1 = __float2bfloat16_rn(x1);
    float r0 = x0 - __bfloat162float(h0);
    float r1 = x1 - __bfloat162float(h1);
    __nv_bfloat16 l0 = __float2bfloat16_rn(r0);
    __nv_bfloat16 l1 = __float2bfloat16_rn(r1);
    hi = (uint32_t)__bfloat16_as_ushort(h0) |
         ((uint32_t)__bfloat16_as_ushort(h1) << 16);
    lo = (uint32_t)__bfloat16_as_ushort(l0) |
         ((uint32_t)__bfloat16_as_ushort(l1) << 16);
}

// ============================================================================
// Emulated-bf16 MMA GEMM, 2 CTAs/SM, BK=64, conflict-free smem.
//  - stride 36 u32 per row: fragment-load banks = 4g+t (all distinct)
//  - B tile XOR swizzle kp^((n>>3)&3): conflict-free STS with n-varying lanes
// Out[M=8192, N] = A[M,1024] @ W[1024,N] + bias, CTA 128x128.
// MODE 0: N=1024, A=g_ao, row-major Out. MODE 1: N=3072, scatter q/k/v.
// ============================================================================
#define KST 36
#define GT64 (128 * KST)                 // u32 per sub-array (4608)
#define GEMM_SMEM_BYTES (4 * GT64 * 4)   // 73728 (72KB/CTA, 2 CTAs = 144KB/SM)

template <int MODE, int NDIM>
__global__ void __launch_bounds__(256, 2) gemm_mma(
    const float* __restrict__ Ain,
    const float* __restrict__ W,
    const float* __restrict__ bias,
    float* __restrict__ Out)
{
    extern __shared__ uint32_t dsm[];
    uint32_t* pAh = dsm;
    uint32_t* pAl = pAh + GT64;
    uint32_t* pBh = pAl + GT64;
    uint32_t* pBl = pBh + GT64;

    const float* A = (MODE == 0) ? g_ao : Ain;

    const int tid = threadIdx.x;
    const int wid = tid >> 5;
    const int lane = tid & 31;
    const int g = lane >> 2;
    const int t = lane & 3;
    const int wm = wid & 3;
    const int wn = wid >> 2;
    const int bm = blockIdx.y * 128;
    const int bn = blockIdx.x * 128;

    // staging coords: A warp covers one row (32 kpairs); B lanes span 32 n's
    const int arow = tid >> 5;           // + i*8 per iter... (see loops)
    const int akp  = tid & 31;
    const int bn_l = tid & 127;
    const int bkp0 = tid >> 7;           // 0 or 1

    float acc[2][8][4];
#pragma unroll
    for (int i = 0; i < 2; i++)
#pragma unroll
        for (int j = 0; j < 8; j++)
#pragma unroll
            for (int c = 0; c < 4; c++) acc[i][j][c] = 0.0f;

    const int bswz = (bn_l >> 3) & 3;    // B store swizzle key

    for (int kc = 0; kc < 16; kc++) {
        const int k0 = kc * 64;
        // ---- stage A: 128 rows x 32 kpairs; one warp per row (no conflicts)
#pragma unroll
        for (int i = 0; i < 16; i++) {
            int row = arow + i * 8;
            float2 v = *(const float2*)&A[(size_t)(bm + row) * 1024 + k0 + akp * 2];
            split2(v.x, v.y, pAh[row * KST + akp], pAl[row * KST + akp]);
        }
        // ---- stage B: transpose w[k][n] -> smem[n][kp^s]; coalesced LDG,
        //      conflict-free STS via swizzle
#pragma unroll
        for (int i = 0; i < 16; i++) {
            int kp = bkp0 + i * 2;
            float w0 = W[(size_t)(k0 + kp * 2) * NDIM + bn + bn_l];
            float w1 = W[(size_t)(k0 + kp * 2 + 1) * NDIM + bn + bn_l];
            int kps = kp ^ bswz;
            split2(w0, w1, pBh[bn_l * KST + kps], pBl[bn_l * KST + kps]);
        }
        __syncthreads();

        // ---- MMAs: 4 k16-steps ----
#pragma unroll
        for (int ks = 0; ks < 4; ks++) {
            const int kp0 = ks * 8;
            uint32_t ah[2][4], al[2][4];
#pragma unroll
            for (int mt = 0; mt < 2; mt++) {
                int r0 = (wm * 32 + mt * 16 + g) * KST;
                ah[mt][0] = pAh[r0 + kp0 + t];
                ah[mt][1] = pAh[r0 + 8 * KST + kp0 + t];
                ah[mt][2] = pAh[r0 + kp0 + t + 4];
                ah[mt][3] = pAh[r0 + 8 * KST + kp0 + t + 4];
                al[mt][0] = pAl[r0 + kp0 + t];
                al[mt][1] = pAl[r0 + 8 * KST + kp0 + t];
                al[mt][2] = pAl[r0 + kp0 + t + 4];
                al[mt][3] = pAl[r0 + 8 * KST + kp0 + t + 4];
            }
#pragma unroll
            for (int nt = 0; nt < 8; nt++) {
                const int s = nt & 3;         // compile-time swizzle key
                int nr = (wn * 64 + nt * 8 + g) * KST;
                uint32_t bh0 = pBh[nr + ((kp0 + t) ^ s)];
                uint32_t bh1 = pBh[nr + ((kp0 + t + 4) ^ s)];
                uint32_t bl0 = pBl[nr + ((kp0 + t) ^ s)];
                uint32_t bl1 = pBl[nr + ((kp0 + t + 4) ^ s)];
#pragma unroll
                for (int mt = 0; mt < 2; mt++) {
                    MMA16816(acc[mt][nt], ah[mt], bh0, bh1);
                    MMA16816(acc[mt][nt], ah[mt], bl0, bl1);
                    MMA16816(acc[mt][nt], al[mt], bh0, bh1);
                }
            }
        }
        __syncthreads();
    }

    // ---- epilogue ----
#pragma unroll
    for (int mt = 0; mt < 2; mt++) {
        int row0 = bm + wm * 32 + mt * 16 + g;
#pragma unroll
        for (int nt = 0; nt < 8; nt++) {
            int col = bn + wn * 64 + nt * 8 + t * 2;
            float b0 = bias[col], b1 = bias[col + 1];
            float2 v0 = make_float2(acc[mt][nt][0] + b0, acc[mt][nt][1] + b1);
            float2 v1 = make_float2(acc[mt][nt][2] + b0, acc[mt][nt][3] + b1);
            if (MODE == 0) {
                *(float2*)&Out[(size_t)row0 * NDIM + col] = v0;
                *(float2*)&Out[(size_t)(row0 + 8) * NDIM + col] = v1;
            } else {
                int which = col >> 10;
                int h = (col & 1023) >> 6;
                int hd = col & 63;
                float* dst = (which == 0) ? g_q : (which == 1) ? g_k : g_v;
                int b = row0 >> 11, s = row0 & 2047;
                *(float2*)&dst[(((size_t)b * H_ + h) * S_ + s) * HD_ + hd] = v0;
                int r1 = row0 + 8;
                b = r1 >> 11; s = r1 & 2047;
                *(float2*)&dst[(((size_t)b * H_ + h) * S_ + s) * HD_ + hd] = v1;
            }
        }
    }
}

// ============================================================================
// Flash attention on emulated-bf16 HMMA, double-buffered K/V (unchanged R10).
// ============================================================================
#define KPV 36
#define QTILE (128 * KPV)
#define KVTILE (64 * KPV)
#define KVBUF (4 * KVTILE)
#define FLASH_SMEM_BYTES ((2 * QTILE + 2 * KVBUF) * 4)

__global__ void __launch_bounds__(256) flash_mma()
{
    extern __shared__ uint32_t su[];
    uint32_t* sQh = su;
    uint32_t* sQl = sQh + QTILE;
    uint32_t* kvbase = sQl + QTILE;

    const int z  = blockIdx.x;
    const int bh = z >> 4;
    const int qt = 15 - (z & 15);
    const int b  = bh >> 4;
    const int h  = bh & 15;

    const int tid = threadIdx.x;
    const int wid = tid >> 5;
    const int lane = tid & 31;
    const int g = lane >> 2;
    const int t = lane & 3;

    const float NEG_INF = __int_as_float(0xff800000);

    const float* kbase = g_k + (size_t)bh * S_ * HD_;
    const float* vbase = g_v + (size_t)bh * S_ * HD_;

    // ---- stage Q (pre-scaled), single buffer ----
    {
        const float* qb = g_q + ((size_t)bh * S_ + qt * 128) * HD_;
#pragma unroll
        for (int i = 0; i < 16; i++) {
            int idx = tid + i * 256;
            int row = idx >> 5, kp = idx & 31;
            float2 v = *(const float2*)&qb[row * 64 + kp * 2];
            split2(v.x * 0.125f, v.y * 0.125f,
                   sQh[row * KPV + kp], sQl[row * KPV + kp]);
        }
    }

    float m0 = NEG_INF, m1 = NEG_INF, l0 = 0.0f, l1 = 0.0f;
    float acco[8][4];
#pragma unroll
    for (int nt = 0; nt < 8; nt++)
#pragma unroll
        for (int c = 0; c < 4; c++) acco[nt][c] = 0.0f;

    const int ktmax = 2 * qt + 1;
    const int rg0 = qt * 128 + wid * 16 + g;
    const int warp_row_hi = qt * 128 + wid * 16 + 15;

    // ---- prologue: stage K/V tile 0 into buffer 0 ----
    {
        uint32_t* pKh = kvbase;
        uint32_t* pKl = pKh + KVTILE;
        uint32_t* pVh = pKl + KVTILE;
        uint32_t* pVl = pVh + KVTILE;
#pragma unroll
        for (int i = 0; i < 8; i++) {
            int idx = tid + i * 256;
            int row = idx >> 5, kp = idx & 31;
            float2 v = *(const float2*)&kbase[(size_t)row * 64 + kp * 2];
            split2(v.x, v.y, pKh[row * KPV + kp], pKl[row * KPV + kp]);
        }
#pragma unroll
        for (int i = 0; i < 8; i++) {
            int idx = tid + i * 256;
            int hd = idx & 63, sp = idx >> 6;
            float v0 = vbase[(size_t)(sp * 2) * 64 + hd];
            float v1 = vbase[(size_t)(sp * 2 + 1) * 64 + hd];
            split2(v0, v1, pVh[hd * KPV + sp], pVl[hd * KPV + sp]);
        }
    }
    __syncthreads();

    float2 rk[8];
    float rv0[8], rv1[8];

    for (int kt = 0; kt <= ktmax; kt++) {
        const int cur = kt & 1;
        const int nxt = cur ^ 1;
        const bool more = (kt < ktmax);

        // ---- issue next K/V tile's global loads ----
        if (more) {
            const float* kbp = kbase + (size_t)(kt + 1) * 64 * HD_;
            const float* vbp = vbase + (size_t)(kt + 1) * 64 * HD_;
#pragma unroll
            for (int i = 0; i < 8; i++) {
                int idx = tid + i * 256;
                int row = idx >> 5, kp = idx & 31;
                rk[i] = *(const float2*)&kbp[(size_t)row * 64 + kp * 2];
            }
#pragma unroll
            for (int i = 0; i < 8; i++) {
                int idx = tid + i * 256;
                int hd = idx & 63, sp = idx >> 6;
                rv0[i] = vbp[(size_t)(sp * 2) * 64 + hd];
                rv1[i] = vbp[(size_t)(sp * 2 + 1) * 64 + hd];
            }
        }

        // ---- compute on current buffer ----
        if (warp_row_hi >= kt * 64) {
            const uint32_t* pKh = kvbase + cur * KVBUF;
            const uint32_t* pKl = pKh + KVTILE;
            const uint32_t* pVh = pKl + KVTILE;
            const uint32_t* pVl = pVh + KVTILE;

            // QK^T
            float accs[8][4];
#pragma unroll
            for (int nt = 0; nt < 8; nt++)
#pragma unroll
                for (int c = 0; c < 4; c++) accs[nt][c] = 0.0f;

#pragma unroll
            for (int ks = 0; ks < 4; ks++) {
                const int r0s = (wid * 16 + g) * KPV;
                const int kpb = ks * 8 + t;
                uint32_t ah[4] = { sQh[r0s + kpb],     sQh[r0s + 8 * KPV + kpb],
                                   sQh[r0s + kpb + 4], sQh[r0s + 8 * KPV + kpb + 4] };
                uint32_t al[4] = { sQl[r0s + kpb],     sQl[r0s + 8 * KPV + kpb],
                                   sQl[r0s + kpb + 4], sQl[r0s + 8 * KPV + kpb + 4] };
#pragma unroll
                for (int nt = 0; nt < 8; nt++) {
                    int nr = (nt * 8 + g) * KPV;
                    uint32_t bh0 = pKh[nr + kpb], bh1 = pKh[nr + kpb + 4];
                    uint32_t bl0 = pKl[nr + kpb], bl1 = pKl[nr + kpb + 4];
                    MMA16816(accs[nt], ah, bh0, bh1);
                    MMA16816(accs[nt], ah, bl0, bl1);
                    MMA16816(accs[nt], al, bh0, bh1);
                }
            }

            // causal mask
            if (kt >= 2 * qt) {
                const int rg1 = rg0 + 8;
#pragma unroll
                for (int nt = 0; nt < 8; nt++) {
                    int c0 = kt * 64 + nt * 8 + t * 2;
                    int c1 = c0 + 1;
                    if (c0 > rg0) accs[nt][0] = NEG_INF;
                    if (c1 > rg0) accs[nt][1] = NEG_INF;
                    if (c0 > rg1) accs[nt][2] = NEG_INF;
                    if (c1 > rg1) accs[nt][3] = NEG_INF;
                }
            }

            // warp-local online softmax
            float rm0 = NEG_INF, rm1 = NEG_INF;
#pragma unroll
            for (int nt = 0; nt < 8; nt++) {
                rm0 = fmaxf(rm0, fmaxf(accs[nt][0], accs[nt][1]));
                rm1 = fmaxf(rm1, fmaxf(accs[nt][2], accs[nt][3]));
            }
            rm0 = fmaxf(rm0, __shfl_xor_sync(0xFFFFFFFF, rm0, 1));
            rm0 = fmaxf(rm0, __shfl_xor_sync(0xFFFFFFFF, rm0, 2));
            rm1 = fmaxf(rm1, __shfl_xor_sync(0xFFFFFFFF, rm1, 1));
            rm1 = fmaxf(rm1, __shfl_xor_sync(0xFFFFFFFF, rm1, 2));

            float mn0 = fmaxf(m0, rm0), mn1 = fmaxf(m1, rm1);
            float a0 = __expf(m0 - mn0);
            float a1 = __expf(m1 - mn1);

            uint32_t pah[4][4], pal[4][4];
            float rs0 = 0.0f, rs1 = 0.0f;
#pragma unroll
            for (int nt = 0; nt < 8; nt++) {
                float p0 = __expf(accs[nt][0] - mn0);
                float p1 = __expf(accs[nt][1] - mn0);
                float p2 = __expf(accs[nt][2] - mn1);
                float p3 = __expf(accs[nt][3] - mn1);
                rs0 += p0 + p1;
                rs1 += p2 + p3;
                uint32_t h01, l01, h23, l23;
                split2(p0, p1, h01, l01);
                split2(p2, p3, h23, l23);
                int ks = nt >> 1, half = nt & 1;
                pah[ks][half * 2]     = h01;
                pah[ks][half * 2 + 1] = h23;
                pal[ks][half * 2]     = l01;
                pal[ks][half * 2 + 1] = l23;
            }
            rs0 += __shfl_xor_sync(0xFFFFFFFF, rs0, 1);
            rs0 += __shfl_xor_sync(0xFFFFFFFF, rs0, 2);
            rs1 += __shfl_xor_sync(0xFFFFFFFF, rs1, 1);
            rs1 += __shfl_xor_sync(0xFFFFFFFF, rs1, 2);

            l0 = l0 * a0 + rs0;
            l1 = l1 * a1 + rs1;
            m0 = mn0;
            m1 = mn1;

#pragma unroll
            for (int nt = 0; nt < 8; nt++) {
                acco[nt][0] *= a0; acco[nt][1] *= a0;
                acco[nt][2] *= a1; acco[nt][3] *= a1;
            }

            // PV
#pragma unroll
            for (int ks = 0; ks < 4; ks++) {
                const int kpb = ks * 8 + t;
#pragma unroll
                for (int nt = 0; nt < 8; nt++) {
                    int nr = (nt * 8 + g) * KPV;
                    uint32_t bh0 = pVh[nr + kpb], bh1 = pVh[nr + kpb + 4];
                    uint32_t bl0 = pVl[nr + kpb], bl1 = pVl[nr + kpb + 4];
                    MMA16816(acco[nt], pah[ks], bh0, bh1);
                    MMA16816(acco[nt], pal[ks], bh0, bh1);
                    MMA16816(acco[nt], pah[ks], bl0, bl1);
                }
            }
        }

        // ---- convert + store next K/V tile ----
        if (more) {
            uint32_t* pKh = kvbase + nxt * KVBUF;
            uint32_t* pKl = pKh + KVTILE;
            uint32_t* pVh = pKl + KVTILE;
            uint32_t* pVl = pVh + KVTILE;
#pragma unroll
            for (int i = 0; i < 8; i++) {
                int idx = tid + i * 256;
                int row = idx >> 5, kp = idx & 31;
                split2(rk[i].x, rk[i].y,
                       pKh[row * KPV + kp], pKl[row * KPV + kp]);
            }
#pragma unroll
            for (int i = 0; i < 8; i++) {
                int idx = tid + i * 256;
                int hd = idx & 63, sp = idx >> 6;
                split2(rv0[i], rv1[i],
                       pVh[hd * KPV + sp], pVl[hd * KPV + sp]);
            }
        }
        __syncthreads();
    }

    // ---- epilogue: O / l -> g_ao[b*s][h*64 + c] ----
    const float i0 = 1.0f / l0;
    const float i1 = 1.0f / l1;
    const int sq = qt * 128 + wid * 16 + g;
#pragma unroll
    for (int nt = 0; nt < 8; nt++) {
        int col = h * 64 + nt * 8 + t * 2;
        float2 v0 = make_float2(acco[nt][0] * i0, acco[nt][1] * i0);
        float2 v1 = make_float2(acco[nt][2] * i1, acco[nt][3] * i1);
        *(float2*)&g_ao[((size_t)b * S_ + sq) * D_ + col] = v0;
        *(float2*)&g_ao[((size_t)b * S_ + sq + 8) * D_ + col] = v1;
    }
}

// ============================================================================
// Launch
// ============================================================================
extern "C" void kernel_launch(void* const* d_in, const int* in_sizes, int n_in,
                              void* d_out, int out_size)
{
    const float *x = nullptr, *w_attn = nullptr, *b_attn = nullptr;
    const float *w_proj = nullptr, *b_proj = nullptr;
    for (int i = 0; i < n_in; i++) {
        switch (in_sizes[i]) {
            case 8388608: x      = (const float*)d_in[i]; break;
            case 3145728: w_attn = (const float*)d_in[i]; break;
            case 3072:    b_attn = (const float*)d_in[i]; break;
            case 1048576: w_proj = (const float*)d_in[i]; break;
            case 1024:    b_proj = (const float*)d_in[i]; break;
            default: break;  // mask (ignored; causal handled analytically)
        }
    }
    if (!x)      x      = (const float*)d_in[0];
    if (!w_attn) w_attn = (const float*)d_in[2];
    if (!b_attn) b_attn = (const float*)d_in[3];
    if (!w_proj) w_proj = (const float*)d_in[4];
    if (!b_proj) b_proj = (const float*)d_in[5];

    const int M = B_ * S_;  // 8192

    cudaFuncSetAttribute(gemm_mma<1, 3072>,
                         cudaFuncAttributeMaxDynamicSharedMemorySize,
                         GEMM_SMEM_BYTES);
    cudaFuncSetAttribute(gemm_mma<0, 1024>,
                         cudaFuncAttributeMaxDynamicSharedMemorySize,
                         GEMM_SMEM_BYTES);
    cudaFuncSetAttribute(flash_mma,
                         cudaFuncAttributeMaxDynamicSharedMemorySize,
                         FLASH_SMEM_BYTES);

    // 1) QKV projection (conflict-free BK=64, 2 CTAs/SM), scatter [b,h,s,hd]
    gemm_mma<1, 3072><<<dim3(3 * D_ / 128, M / 128), 256, GEMM_SMEM_BYTES>>>(
        x, w_attn, b_attn, nullptr);

    // 2) Fused causal flash attention (pipelined emulated-bf16 MMA)
    flash_mma<<<B_ * H_ * (S_ / 128), 256, FLASH_SMEM_BYTES>>>();

    // 3) Output projection -> d_out
    gemm_mma<0, 1024><<<dim3(D_ / 128, M / 128), 256, GEMM_SMEM_BYTES>>>(
        nullptr, w_proj, b_proj, (float*)d_out);
}